// round 1
// baseline (speedup 1.0000x reference)
#include <cuda_runtime.h>
#include <cstdint>

// Problem constants (fixed by dataset: x[N,256], W[256,128], b[128], out[N,64])
#define D_IN   256
#define C_OUT  128
#define KDIM   32
#define EPSV   1e-6f

#define TM      128      // rows per block in pass1
#define THREADS 256
#define MAXB    4096     // max pass1 blocks supported (N <= 524288)
#define NPART   1088     // 1024 VtZ + 32 sumU + 32 sumV

// Scratch: per-block partials, transposed [output][block] for coalesced reduce.
__device__ float g_part[(size_t)NPART * MAXB];
__device__ float g_red[NPART];

typedef unsigned long long u64;

__device__ __forceinline__ u64 pk(float lo, float hi) {
    u64 r; asm("mov.b64 %0,{%1,%2};" : "=l"(r) : "f"(lo), "f"(hi)); return r;
}
__device__ __forceinline__ void upk(u64 v, float& lo, float& hi) {
    asm("mov.b64 {%0,%1},%2;" : "=f"(lo), "=f"(hi) : "l"(v));
}
// Packed dual-FMA: full-rate fp32 on sm_103a (3-reg FFMA is half rate).
__device__ __forceinline__ void fma2(u64& d, u64 a, u64 b) {
    asm("fma.rn.f32x2 %0,%1,%2,%0;" : "+l"(d) : "l"(a), "l"(b));
}

// ---------------------------------------------------------------------------
// Pass 1: X = relu(x@W + b). Writes U -> out[:,0:32], T -> out[:,32:64].
// Accumulates per-block partials of colsum(U), colsum(V), V^T Z.
// Block: 256 threads, tile 128 rows x 128 cols, K-chunks of 32.
// Thread (i = tid>>4, j = tid&15): rows {i+16m, m=0..7}, cols {8j..8j+7}.
// ---------------------------------------------------------------------------
__global__ __launch_bounds__(THREADS, 2)
void pass1_kernel(const float* __restrict__ x, const float* __restrict__ W,
                  const float* __restrict__ b, float* __restrict__ out, int N)
{
    // Phase A: xs[128][36] (4608) + ws[32][128] (4096) = 8704 floats
    // Phase B: vs[128][33] (4224) + zs[128][34] (4352) + red[16][64] (1024) = 9600
    __shared__ __align__(16) float sm[9600];
    float* xs = sm;                 // [128][36] padded
    float* ws = sm + 128 * 36;      // [32][128]

    const int tid = threadIdx.x;
    const int i = tid >> 4;         // 0..15 (row group)
    const int j = tid & 15;         // 0..15 (col group, 8 cols each)
    const int r0 = blockIdx.x * TM;

    u64 acc[8][4];
#pragma unroll
    for (int m = 0; m < 8; m++)
#pragma unroll
        for (int c = 0; c < 4; c++) acc[m][c] = 0ull;

    for (int kt = 0; kt < 8; kt++) {
        const int k0 = kt * 32;
        // Load x tile [128 rows x 32 k] -> xs (padded stride 36), guarded.
#pragma unroll
        for (int q = 0; q < 4; q++) {
            int f = tid + 256 * q;          // 0..1023 float4 slots
            int row = f >> 3, kk4 = (f & 7) * 4;
            int grow = r0 + row;
            float4 v = make_float4(0.f, 0.f, 0.f, 0.f);
            if (grow < N)
                v = *(const float4*)(x + (size_t)grow * D_IN + k0 + kk4);
            *(float4*)(xs + row * 36 + kk4) = v;
        }
        // Load W tile [32 k x 128 cols] -> ws.
#pragma unroll
        for (int q = 0; q < 4; q++) {
            int f = tid + 256 * q;
            int kr = f >> 5, c4 = (f & 31) * 4;
            *(float4*)(ws + kr * 128 + c4) =
                *(const float4*)(W + (size_t)(k0 + kr) * C_OUT + c4);
        }
        __syncthreads();

#pragma unroll 8
        for (int kk = 0; kk < 32; kk += 2) {
            u64 wv[2][4];
#pragma unroll
            for (int t = 0; t < 2; t++) {
                float4 w0 = *(float4*)(ws + (kk + t) * 128 + 8 * j);
                float4 w1 = *(float4*)(ws + (kk + t) * 128 + 8 * j + 4);
                wv[t][0] = pk(w0.x, w0.y); wv[t][1] = pk(w0.z, w0.w);
                wv[t][2] = pk(w1.x, w1.y); wv[t][3] = pk(w1.z, w1.w);
            }
#pragma unroll
            for (int m = 0; m < 8; m++) {
                u64 xp = *(u64*)(xs + (i + 16 * m) * 36 + kk);  // (x_k, x_{k+1})
                float xlo, xhi; upk(xp, xlo, xhi);
                u64 a0 = pk(xlo, xlo), a1 = pk(xhi, xhi);
#pragma unroll
                for (int c = 0; c < 4; c++) {
                    fma2(acc[m][c], a0, wv[0][c]);
                    fma2(acc[m][c], a1, wv[1][c]);
                }
            }
        }
        __syncthreads();
    }

    // Bias + relu; zero out-of-range rows so reductions stay exact.
    float bias[8];
#pragma unroll
    for (int t = 0; t < 8; t++) bias[t] = b[8 * j + t];

    float X[8][8];
#pragma unroll
    for (int m = 0; m < 8; m++) {
        const bool valid = (r0 + i + 16 * m) < N;
#pragma unroll
        for (int c = 0; c < 4; c++) {
            float lo, hi; upk(acc[m][c], lo, hi);
            float v0 = fmaxf(lo + bias[2 * c], 0.f);
            float v1 = fmaxf(hi + bias[2 * c + 1], 0.f);
            X[m][2 * c]     = valid ? v0 : 0.f;
            X[m][2 * c + 1] = valid ? v1 : 0.f;
        }
    }

    // Store U (cols 0..31) to out[:,0:32] (scratch-in-output) and
    // T (cols 96..127) to out[:,32:64].
    if (j < 4) {
#pragma unroll
        for (int m = 0; m < 8; m++) {
            int grow = r0 + i + 16 * m;
            if (grow < N) {
                *(float4*)(out + (size_t)grow * 64 + 8 * j) =
                    make_float4(X[m][0], X[m][1], X[m][2], X[m][3]);
                *(float4*)(out + (size_t)grow * 64 + 8 * j + 4) =
                    make_float4(X[m][4], X[m][5], X[m][6], X[m][7]);
            }
        }
    } else if (j >= 12) {
        // global col = 8j-96+t  ->  out col = 32 + (8j-96)+t = 8j-64+t
#pragma unroll
        for (int m = 0; m < 8; m++) {
            int grow = r0 + i + 16 * m;
            if (grow < N) {
                *(float4*)(out + (size_t)grow * 64 + 8 * j - 64) =
                    make_float4(X[m][0], X[m][1], X[m][2], X[m][3]);
                *(float4*)(out + (size_t)grow * 64 + 8 * j - 60) =
                    make_float4(X[m][4], X[m][5], X[m][6], X[m][7]);
            }
        }
    }

    // ---- Phase B: block-local reductions (smem reuse is safe: last
    // __syncthreads above guarantees all xs/ws reads are done). ----
    float* vs  = sm;                   // [128][33]
    float* zs  = sm + 128 * 33;        // [128][34] (even stride for LDS.64)
    float* red = sm + 128 * 33 + 128 * 34;  // [16][64]

    if (j >= 4 && j < 8) {
#pragma unroll
        for (int m = 0; m < 8; m++) {
            int row = i + 16 * m;
#pragma unroll
            for (int t = 0; t < 8; t++) vs[row * 33 + 8 * (j - 4) + t] = X[m][t];
        }
    }
    if (j >= 8 && j < 12) {
#pragma unroll
        for (int m = 0; m < 8; m++) {
            int row = i + 16 * m;
#pragma unroll
            for (int t = 0; t < 8; t++) zs[row * 34 + 8 * (j - 8) + t] = X[m][t];
        }
    }
    // Column-sum partials for U (j<4) and V (4<=j<8).
    if (j < 8) {
#pragma unroll
        for (int t = 0; t < 8; t++) {
            float s = 0.f;
#pragma unroll
            for (int m = 0; m < 8; m++) s += X[m][t];
            red[i * 64 + 8 * j + t] = s;
        }
    }
    __syncthreads();

    // VtZ: thread handles k in {2i, 2i+1}, cols {2j, 2j+1} over 128 rows.
    {
        const int kk0 = 2 * i, jj0 = 2 * j;
        u64 a0 = 0ull, a1 = 0ull;
#pragma unroll 4
        for (int row = 0; row < 128; row++) {
            float v0 = vs[row * 33 + kk0];
            float v1 = vs[row * 33 + kk0 + 1];
            u64 zz = *(u64*)(zs + row * 34 + jj0);
            fma2(a0, pk(v0, v0), zz);
            fma2(a1, pk(v1, v1), zz);
        }
        float p00, p01, p10, p11;
        upk(a0, p00, p01); upk(a1, p10, p11);
        const int blk = blockIdx.x;
        g_part[(size_t)(kk0 * 32 + jj0)     * MAXB + blk] = p00;
        g_part[(size_t)(kk0 * 32 + jj0 + 1) * MAXB + blk] = p01;
        g_part[(size_t)((kk0 + 1) * 32 + jj0)     * MAXB + blk] = p10;
        g_part[(size_t)((kk0 + 1) * 32 + jj0 + 1) * MAXB + blk] = p11;
    }
    // Column sums (64 outputs: sumU[0:32], sumV[32:64]).
    if (tid < 64) {
        float s = 0.f;
#pragma unroll
        for (int q = 0; q < 16; q++) s += red[q * 64 + tid];
        g_part[(size_t)(1024 + tid) * MAXB + blockIdx.x] = s;
    }
}

// ---------------------------------------------------------------------------
// Pass 2: deterministic reduction. One warp per output; fixed lane order +
// fixed shuffle tree => bitwise deterministic across replays.
// ---------------------------------------------------------------------------
__global__ void reduce_kernel(int nb)
{
    int gtid = blockIdx.x * blockDim.x + threadIdx.x;
    int warp = gtid >> 5;
    int lane = gtid & 31;
    if (warp >= NPART) return;
    const float* p = g_part + (size_t)warp * MAXB;
    float s = 0.f;
    for (int bq = lane; bq < nb; bq += 32) s += p[bq];
#pragma unroll
    for (int off = 16; off; off >>= 1)
        s += __shfl_down_sync(0xffffffffu, s, off);
    if (lane == 0) g_red[warp] = s;
}

// ---------------------------------------------------------------------------
// Pass 3: in-place out[:,0:32] = U @ (VtZ * D), D = 1/(sumU.sumV/N + eps).
// One row per thread; M = VtZ*D in smem (stride 34 for aligned LDS.64).
// ---------------------------------------------------------------------------
__global__ __launch_bounds__(THREADS)
void pass3_kernel(float* __restrict__ out, int N)
{
    __shared__ __align__(16) float M[32 * 34];
    __shared__ float sD;
    const int tid = threadIdx.x;

    if (tid < 32) {
        float p = g_red[1024 + tid] * g_red[1056 + tid];
#pragma unroll
        for (int off = 16; off; off >>= 1)
            p += __shfl_down_sync(0xffffffffu, p, off);
        if (tid == 0) sD = 1.0f / (p / (float)N + EPSV);
    }
    __syncthreads();
    const float D = sD;
#pragma unroll
    for (int q = tid; q < 1024; q += THREADS) {
        int k = q >> 5, c = q & 31;
        M[k * 34 + c] = g_red[q] * D;
    }
    __syncthreads();

    const int row = blockIdx.x * THREADS + tid;
    if (row >= N) return;

    float u[32];
#pragma unroll
    for (int t = 0; t < 8; t++)
        ((float4*)u)[t] = *(const float4*)(out + (size_t)row * 64 + 4 * t);

    u64 acc[16];
#pragma unroll
    for (int c = 0; c < 16; c++) acc[c] = 0ull;

#pragma unroll
    for (int k = 0; k < 32; k++) {
        u64 a = pk(u[k], u[k]);
#pragma unroll
        for (int c = 0; c < 16; c++)
            fma2(acc[c], a, *(u64*)(M + k * 34 + 2 * c));
    }

#pragma unroll
    for (int c = 0; c < 8; c++) {
        float r0, r1, r2, r3;
        upk(acc[2 * c], r0, r1);
        upk(acc[2 * c + 1], r2, r3);
        *(float4*)(out + (size_t)row * 64 + 4 * c) = make_float4(r0, r1, r2, r3);
    }
}

// ---------------------------------------------------------------------------
extern "C" void kernel_launch(void* const* d_in, const int* in_sizes, int n_in,
                              void* d_out, int out_size)
{
    const float* x = (const float*)d_in[0];
    const float* W = (const float*)d_in[1];
    const float* b = (const float*)d_in[2];
    float* out = (float*)d_out;

    const int N  = in_sizes[0] / D_IN;
    const int nb = (N + TM - 1) / TM;          // <= MAXB for this dataset

    pass1_kernel<<<nb, THREADS>>>(x, W, b, out, N);
    reduce_kernel<<<(NPART * 32 + THREADS - 1) / THREADS, THREADS>>>(nb);
    pass3_kernel<<<(N + THREADS - 1) / THREADS, THREADS>>>(out, N);
}

// round 4
// speedup vs baseline: 1.6377x; 1.6377x over previous
#include <cuda_runtime.h>
#include <cuda_bf16.h>
#include <cstdint>

typedef unsigned int u32;
typedef unsigned long long u64;

// Problem constants (x[N,256], W[256,128], b[128], out[N,64])
#define D_IN   256
#define C_OUT  128
#define EPSV   1e-6f
#define TM     128
#define THREADS 256
#define MAXB   4096
#define NPART  1088          // 1024 VtZ + 32 sumU + 32 sumV
#define KC     64            // K elems per chunk
#define NCH    4             // 256 / 64

// bf16 tile 128 x 64, padded row stride 72 elems (144 B) -> conflict-free ldmatrix
#define AST      72
#define RB       (AST * 2)           // row bytes = 144
#define TILE_B   (128 * RB)          // 18432 B
#define WREG_B   (8 * TILE_B)        // 4 chunks x (hi,lo) = 147456 B
#define XBUF_B   (2 * TILE_B)        // (hi,lo) per buffer
#define XOFF     WREG_B
#define DSM_B    (WREG_B + 2 * XBUF_B)   // 221184 B

__device__ float g_part[(size_t)NPART * MAXB];
__device__ float g_red[NPART];
__device__ __nv_bfloat16 g_Whi[C_OUT * D_IN];   // [n][k] K-major
__device__ __nv_bfloat16 g_Wlo[C_OUT * D_IN];

// ---------------------------------------------------------------------------
// helpers
// ---------------------------------------------------------------------------
__device__ __forceinline__ u32 smem_u32(const void* p) {
    u32 a; asm("{ .reg .u64 t; cvta.to.shared.u64 t, %1; cvt.u32.u64 %0, t; }"
               : "=r"(a) : "l"(p));
    return a;
}
__device__ __forceinline__ void sts8(u32 addr, u32 a, u32 b) {
    asm volatile("st.shared.v2.u32 [%0], {%1,%2};" :: "r"(addr), "r"(a), "r"(b) : "memory");
}
__device__ __forceinline__ void sts64(u32 addr, u64 v) {
    asm volatile("st.shared.b64 [%0], %1;" :: "r"(addr), "l"(v) : "memory");
}
__device__ __forceinline__ void ldm_x4(u32 a, u32& r0, u32& r1, u32& r2, u32& r3) {
    asm volatile("ldmatrix.sync.aligned.m8n8.x4.shared.b16 {%0,%1,%2,%3}, [%4];"
                 : "=r"(r0), "=r"(r1), "=r"(r2), "=r"(r3) : "r"(a));
}
__device__ __forceinline__ void ldm_x2(u32 a, u32& r0, u32& r1) {
    asm volatile("ldmatrix.sync.aligned.m8n8.x2.shared.b16 {%0,%1}, [%2];"
                 : "=r"(r0), "=r"(r1) : "r"(a));
}
__device__ __forceinline__ void mma16816(float& c0, float& c1, float& c2, float& c3,
                                         u32 a0, u32 a1, u32 a2, u32 a3,
                                         u32 b0, u32 b1) {
    asm volatile("mma.sync.aligned.m16n8k16.row.col.f32.bf16.bf16.f32 "
                 "{%0,%1,%2,%3}, {%4,%5,%6,%7}, {%8,%9}, {%0,%1,%2,%3};"
                 : "+f"(c0), "+f"(c1), "+f"(c2), "+f"(c3)
                 : "r"(a0), "r"(a1), "r"(a2), "r"(a3), "r"(b0), "r"(b1));
}
// fp32x2 packed helpers
__device__ __forceinline__ u64 pk(float lo, float hi) {
    u64 r; asm("mov.b64 %0,{%1,%2};" : "=l"(r) : "f"(lo), "f"(hi)); return r;
}
__device__ __forceinline__ void upk(u64 v, float& lo, float& hi) {
    asm("mov.b64 {%0,%1},%2;" : "=f"(lo), "=f"(hi) : "l"(v));
}
__device__ __forceinline__ void fma2(u64& d, u64 a, u64 b) {
    asm("fma.rn.f32x2 %0,%1,%2,%0;" : "+l"(d) : "l"(a), "l"(b));
}
__device__ __forceinline__ u32 pack_bf16x2(float lo, float hi) {
    u32 r; asm("cvt.rn.bf16x2.f32 %0, %1, %2;" : "=r"(r) : "f"(hi), "f"(lo)); return r;
}

// ---------------------------------------------------------------------------
// W split prologue: g_Whi/g_Wlo[n][k] = bf16 split of W[k][n]
// ---------------------------------------------------------------------------
__global__ void wsplit_kernel(const float* __restrict__ W) {
    int idx = blockIdx.x * blockDim.x + threadIdx.x;
    if (idx >= D_IN * C_OUT) return;
    int k = idx / C_OUT, n = idx % C_OUT;
    float w = W[idx];
    __nv_bfloat16 h = __float2bfloat16_rn(w);
    float l = w - __bfloat162float(h);
    g_Whi[n * D_IN + k] = h;
    g_Wlo[n * D_IN + k] = __float2bfloat16_rn(l);
}

// ---------------------------------------------------------------------------
// Pass 1: X = relu(x@W + b) via bf16-split mma.sync (3 terms: hh + hl + lh).
// CTA: 128 rows x 128 cols; 8 warps, warp tile 32(m) x 64(n).
// W (all 4 K-chunks, hi+lo) staged once in smem; x double-buffered.
// Epilogue: U->out[:,0:32], T->out[:,32:64], V/Z->smem, VtZ+colsums->g_part.
// ---------------------------------------------------------------------------
__global__ __launch_bounds__(THREADS, 1)
void pass1_kernel(const float* __restrict__ x, const float* __restrict__ b,
                  float* __restrict__ out, int N)
{
    extern __shared__ __align__(16) char dsm[];
    __shared__ float s_b[C_OUT];

    const int tid = threadIdx.x, lane = tid & 31, wid = tid >> 5;
    const int wm = wid & 3, wn = wid >> 2;     // warp tile coords
    const int r0 = blockIdx.x * TM;
    const u32 base = smem_u32(dsm);

    if (tid < C_OUT) s_b[tid] = b[tid];

    // ---- stage all of W (hi+lo, 4 chunks) into smem ----
#pragma unroll
    for (int q = 0; q < 32; q++) {
        int u = tid + 256 * q;                 // 8192 u64 units per split
        int n = u >> 6;                        // 0..127
        int kk = (u & 63) * 4;                 // 0..252
        int ch = kk >> 6, ko = kk & 63;        // chunk, k-within
        u32 dst = base + ch * (2 * TILE_B) + n * RB + ko * 2;
        sts64(dst, *(const u64*)(g_Whi + n * D_IN + kk));
        sts64(dst + TILE_B, *(const u64*)(g_Wlo + n * D_IN + kk));
    }

    float acc[2][8][4];
#pragma unroll
    for (int mt = 0; mt < 2; mt++)
#pragma unroll
        for (int nt = 0; nt < 8; nt++)
#pragma unroll
            for (int q = 0; q < 4; q++) acc[mt][nt][q] = 0.f;

    float4 xr[8];

    auto ldg = [&](int c) {
        const float* xp = x + (size_t)r0 * D_IN + c * KC;
#pragma unroll
        for (int q = 0; q < 8; q++) {
            int f = tid + 256 * q;                 // 2048 float4 slots
            int row = f >> 4, c4 = (f & 15) * 4;
            xr[q] = make_float4(0.f, 0.f, 0.f, 0.f);
            if (r0 + row < N) xr[q] = *(const float4*)(xp + (size_t)row * D_IN + c4);
        }
    };
    auto sts = [&](u32 xbuf) {
        const u32 ahi = base + XOFF + xbuf, alo = ahi + TILE_B;
#pragma unroll
        for (int q = 0; q < 8; q++) {
            int f = tid + 256 * q;
            int row = f >> 4, c4 = (f & 15) * 4;
            float4 v = xr[q];
            __nv_bfloat16 h0 = __float2bfloat16_rn(v.x);
            __nv_bfloat16 h1 = __float2bfloat16_rn(v.y);
            __nv_bfloat16 h2 = __float2bfloat16_rn(v.z);
            __nv_bfloat16 h3 = __float2bfloat16_rn(v.w);
            u32 hA = ((u32)__bfloat16_as_ushort(h1) << 16) | __bfloat16_as_ushort(h0);
            u32 hB = ((u32)__bfloat16_as_ushort(h3) << 16) | __bfloat16_as_ushort(h2);
            u32 lA = pack_bf16x2(v.x - __bfloat162float(h0), v.y - __bfloat162float(h1));
            u32 lB = pack_bf16x2(v.z - __bfloat162float(h2), v.w - __bfloat162float(h3));
            u32 off = row * RB + c4 * 2;
            sts8(ahi + off, hA, hB);
            sts8(alo + off, lA, lB);
        }
    };
    auto mma_chunk = [&](int c, u32 xbuf) {
        const u32 ahi = base + XOFF + xbuf, alo = ahi + TILE_B;
        const u32 bhi = base + c * (2 * TILE_B), blo = bhi + TILE_B;
        const u32 aoff = (wm * 32 + (lane & 15)) * RB + (lane >> 4) * 16;
        const u32 boff = (wn * 64 + (lane & 7)) * RB + ((lane >> 3) & 1) * 16;
#pragma unroll
        for (int ks = 0; ks < 4; ks++) {
            u32 ah[2][4], al[2][4];
            ldm_x4(ahi + aoff + ks * 32,           ah[0][0], ah[0][1], ah[0][2], ah[0][3]);
            ldm_x4(ahi + aoff + 16 * RB + ks * 32, ah[1][0], ah[1][1], ah[1][2], ah[1][3]);
            ldm_x4(alo + aoff + ks * 32,           al[0][0], al[0][1], al[0][2], al[0][3]);
            ldm_x4(alo + aoff + 16 * RB + ks * 32, al[1][0], al[1][1], al[1][2], al[1][3]);
#pragma unroll
            for (int nt = 0; nt < 8; nt++) {
                u32 bh0, bh1, bl0, bl1;
                ldm_x2(bhi + boff + nt * 8 * RB + ks * 32, bh0, bh1);
                ldm_x2(blo + boff + nt * 8 * RB + ks * 32, bl0, bl1);
#pragma unroll
                for (int mt = 0; mt < 2; mt++) {
                    mma16816(acc[mt][nt][0], acc[mt][nt][1], acc[mt][nt][2], acc[mt][nt][3],
                             ah[mt][0], ah[mt][1], ah[mt][2], ah[mt][3], bh0, bh1);
                    mma16816(acc[mt][nt][0], acc[mt][nt][1], acc[mt][nt][2], acc[mt][nt][3],
                             ah[mt][0], ah[mt][1], ah[mt][2], ah[mt][3], bl0, bl1);
                    mma16816(acc[mt][nt][0], acc[mt][nt][1], acc[mt][nt][2], acc[mt][nt][3],
                             al[mt][0], al[mt][1], al[mt][2], al[mt][3], bh0, bh1);
                }
            }
        }
    };

    // software pipeline over x chunks: LDG(c+1) || MMA(c)
    ldg(0);
    sts(0);
    __syncthreads();
#pragma unroll
    for (int c = 0; c < NCH; c++) {
        if (c < NCH - 1) ldg(c + 1);
        mma_chunk(c, (c & 1) * XBUF_B);
        if (c < NCH - 1) sts(((c + 1) & 1) * XBUF_B);
        __syncthreads();
    }

    // ---- epilogue ----
    float* vs   = (float*)dsm;              // [128][34]
    float* zs   = vs + 128 * 34;            // [128][34]
    float* redU = zs + 128 * 34;            // [4][32]
    float* redV = redU + 128;               // [4][32]

#pragma unroll
    for (int nt = 0; nt < 8; nt++) {
        const int colb = wn * 64 + nt * 8 + (lane & 3) * 2;
        const float b0 = s_b[colb], b1 = s_b[colb + 1];
        float v[2][4];
        int rl[2];
#pragma unroll
        for (int mt = 0; mt < 2; mt++) {
            rl[mt] = wm * 32 + mt * 16 + (lane >> 2);
            const bool ok1 = (r0 + rl[mt]) < N, ok2 = (r0 + rl[mt] + 8) < N;
            v[mt][0] = ok1 ? fmaxf(acc[mt][nt][0] + b0, 0.f) : 0.f;
            v[mt][1] = ok1 ? fmaxf(acc[mt][nt][1] + b1, 0.f) : 0.f;
            v[mt][2] = ok2 ? fmaxf(acc[mt][nt][2] + b0, 0.f) : 0.f;
            v[mt][3] = ok2 ? fmaxf(acc[mt][nt][3] + b1, 0.f) : 0.f;
        }
        if (wn == 0) {
            if (nt < 4) {
                // U -> out[:, colb], colb in 0..31
#pragma unroll
                for (int mt = 0; mt < 2; mt++) {
                    if (r0 + rl[mt] < N)
                        *(float2*)(out + (size_t)(r0 + rl[mt]) * 64 + colb) =
                            make_float2(v[mt][0], v[mt][1]);
                    if (r0 + rl[mt] + 8 < N)
                        *(float2*)(out + (size_t)(r0 + rl[mt] + 8) * 64 + colb) =
                            make_float2(v[mt][2], v[mt][3]);
                }
                float s0 = v[0][0] + v[0][2] + v[1][0] + v[1][2];
                float s1 = v[0][1] + v[0][3] + v[1][1] + v[1][3];
                s0 += __shfl_down_sync(0xffffffffu, s0, 16);
                s0 += __shfl_down_sync(0xffffffffu, s0, 8);
                s0 += __shfl_down_sync(0xffffffffu, s0, 4);
                s1 += __shfl_down_sync(0xffffffffu, s1, 16);
                s1 += __shfl_down_sync(0xffffffffu, s1, 8);
                s1 += __shfl_down_sync(0xffffffffu, s1, 4);
                if (lane < 4) {
                    redU[wm * 32 + nt * 8 + lane * 2]     = s0;
                    redU[wm * 32 + nt * 8 + lane * 2 + 1] = s1;
                }
            } else {
                // V -> vs[:, colb-32]
                const int vc = colb - 32;
#pragma unroll
                for (int mt = 0; mt < 2; mt++) {
                    *(float2*)(vs + rl[mt] * 34 + vc)       = make_float2(v[mt][0], v[mt][1]);
                    *(float2*)(vs + (rl[mt] + 8) * 34 + vc) = make_float2(v[mt][2], v[mt][3]);
                }
                float s0 = v[0][0] + v[0][2] + v[1][0] + v[1][2];
                float s1 = v[0][1] + v[0][3] + v[1][1] + v[1][3];
                s0 += __shfl_down_sync(0xffffffffu, s0, 16);
                s0 += __shfl_down_sync(0xffffffffu, s0, 8);
                s0 += __shfl_down_sync(0xffffffffu, s0, 4);
                s1 += __shfl_down_sync(0xffffffffu, s1, 16);
                s1 += __shfl_down_sync(0xffffffffu, s1, 8);
                s1 += __shfl_down_sync(0xffffffffu, s1, 4);
                if (lane < 4) {
                    redV[wm * 32 + (nt - 4) * 8 + lane * 2]     = s0;
                    redV[wm * 32 + (nt - 4) * 8 + lane * 2 + 1] = s1;
                }
            }
        } else {
            if (nt < 4) {
                // Z -> zs[:, colb-64]
                const int zc = colb - 64;
#pragma unroll
                for (int mt = 0; mt < 2; mt++) {
                    *(float2*)(zs + rl[mt] * 34 + zc)       = make_float2(v[mt][0], v[mt][1]);
                    *(float2*)(zs + (rl[mt] + 8) * 34 + zc) = make_float2(v[mt][2], v[mt][3]);
                }
            } else {
                // T -> out[:, colb-64] (cols 32..63)
                const int tc = colb - 64;
#pragma unroll
                for (int mt = 0; mt < 2; mt++) {
                    if (r0 + rl[mt] < N)
                        *(float2*)(out + (size_t)(r0 + rl[mt]) * 64 + tc) =
                            make_float2(v[mt][0], v[mt][1]);
                    if (r0 + rl[mt] + 8 < N)
                        *(float2*)(out + (size_t)(r0 + rl[mt] + 8) * 64 + tc) =
                            make_float2(v[mt][2], v[mt][3]);
                }
            }
        }
    }
    __syncthreads();

    // ---- VtZ partials ----
    {
        const int i2 = tid >> 4, j2 = tid & 15;
        const int kk0 = 2 * i2, jj0 = 2 * j2;
        u64 a0 = 0ull, a1 = 0ull;
#pragma unroll 4
        for (int row = 0; row < 128; row++) {
            float v0 = vs[row * 34 + kk0];
            float v1 = vs[row * 34 + kk0 + 1];
            u64 zz = *(u64*)(zs + row * 34 + jj0);
            fma2(a0, pk(v0, v0), zz);
            fma2(a1, pk(v1, v1), zz);
        }
        float p00, p01, p10, p11;
        upk(a0, p00, p01); upk(a1, p10, p11);
        const int blk = blockIdx.x;
        g_part[(size_t)(kk0 * 32 + jj0)           * MAXB + blk] = p00;
        g_part[(size_t)(kk0 * 32 + jj0 + 1)       * MAXB + blk] = p01;
        g_part[(size_t)((kk0 + 1) * 32 + jj0)     * MAXB + blk] = p10;
        g_part[(size_t)((kk0 + 1) * 32 + jj0 + 1) * MAXB + blk] = p11;
    }
    // colsum partials
    if (tid < 32) {
        float s = redU[tid] + redU[32 + tid] + redU[64 + tid] + redU[96 + tid];
        g_part[(size_t)(1024 + tid) * MAXB + blockIdx.x] = s;
    } else if (tid < 64) {
        int t = tid - 32;
        float s = redV[t] + redV[32 + t] + redV[64 + t] + redV[96 + t];
        g_part[(size_t)(1056 + t) * MAXB + blockIdx.x] = s;
    }
}

// ---------------------------------------------------------------------------
// Pass 2: deterministic reduction (one warp per output, fixed shuffle tree)
// ---------------------------------------------------------------------------
__global__ void reduce_kernel(int nb)
{
    int gtid = blockIdx.x * blockDim.x + threadIdx.x;
    int warp = gtid >> 5, lane = gtid & 31;
    if (warp >= NPART) return;
    const float* p = g_part + (size_t)warp * MAXB;
    float s = 0.f;
    for (int bq = lane; bq < nb; bq += 32) s += p[bq];
#pragma unroll
    for (int off = 16; off; off >>= 1)
        s += __shfl_down_sync(0xffffffffu, s, off);
    if (lane == 0) g_red[warp] = s;
}

// ---------------------------------------------------------------------------
// Pass 3: out[:,0:32] = U @ (VtZ * D) in place
// ---------------------------------------------------------------------------
__global__ __launch_bounds__(THREADS)
void pass3_kernel(float* __restrict__ out, int N)
{
    __shared__ __align__(16) float M[32 * 34];
    __shared__ float sD;
    const int tid = threadIdx.x;

    if (tid < 32) {
        float p = g_red[1024 + tid] * g_red[1056 + tid];
#pragma unroll
        for (int off = 16; off; off >>= 1)
            p += __shfl_down_sync(0xffffffffu, p, off);
        if (tid == 0) sD = 1.0f / (p / (float)N + EPSV);
    }
    __syncthreads();
    const float D = sD;
#pragma unroll
    for (int q = tid; q < 1024; q += THREADS) {
        int k = q >> 5, c = q & 31;
        M[k * 34 + c] = g_red[q] * D;
    }
    __syncthreads();

    const int row = blockIdx.x * THREADS + tid;
    if (row >= N) return;

    float u[32];
#pragma unroll
    for (int t = 0; t < 8; t++)
        ((float4*)u)[t] = *(const float4*)(out + (size_t)row * 64 + 4 * t);

    u64 acc[16];
#pragma unroll
    for (int c = 0; c < 16; c++) acc[c] = 0ull;
#pragma unroll
    for (int k = 0; k < 32; k++) {
        u64 a = pk(u[k], u[k]);
#pragma unroll
        for (int c = 0; c < 16; c++)
            fma2(acc[c], a, *(u64*)(M + k * 34 + 2 * c));
    }
#pragma unroll
    for (int c = 0; c < 8; c++) {
        float r0, r1, r2, r3;
        upk(acc[2 * c], r0, r1);
        upk(acc[2 * c + 1], r2, r3);
        *(float4*)(out + (size_t)row * 64 + 4 * c) = make_float4(r0, r1, r2, r3);
    }
}

// ---------------------------------------------------------------------------
extern "C" void kernel_launch(void* const* d_in, const int* in_sizes, int n_in,
                              void* d_out, int out_size)
{
    const float* x = (const float*)d_in[0];
    const float* W = (const float*)d_in[1];
    const float* b = (const float*)d_in[2];
    float* out = (float*)d_out;

    const int N  = in_sizes[0] / D_IN;
    const int nb = (N + TM - 1) / TM;

    cudaFuncSetAttribute(pass1_kernel,
                         cudaFuncAttributeMaxDynamicSharedMemorySize, DSM_B);

    wsplit_kernel<<<(D_IN * C_OUT + 255) / 256, 256>>>(W);
    pass1_kernel<<<nb, THREADS, DSM_B>>>(x, b, out, N);
    reduce_kernel<<<(NPART * 32 + THREADS - 1) / THREADS, THREADS>>>(nb);
    pass3_kernel<<<(N + THREADS - 1) / THREADS, THREADS>>>(out, N);
}

// round 5
// speedup vs baseline: 2.4066x; 1.4695x over previous
#include <cuda_runtime.h>
#include <cuda_fp16.h>
#include <cstdint>

typedef unsigned int u32;
typedef unsigned long long u64;

// Problem constants (x[N,256], W[256,128], b[128], out[N,64])
#define D_IN   256
#define C_OUT  128
#define EPSV   1e-6f
#define TM     128
#define THREADS 256
#define MAXB   4096
#define NPART  1088          // 1024 VtZ + 32 sumU + 32 sumV
#define KC     64            // K elems per chunk
#define NCH    4             // 256 / 64

// fp16 tile 128 x 64, padded row stride 72 elems (144 B) -> conflict-free ldmatrix
#define AST      72
#define RB       (AST * 2)           // row bytes = 144
#define TILE_B   (128 * RB)          // 18432 B
#define XOFF     (4 * TILE_B)        // W: 4 chunks staged once
#define DSM_B    (XOFF + 2 * TILE_B) // 110592 B -> 2 CTAs/SM

__device__ float g_part[(size_t)NPART * MAXB];
__device__ float g_red[NPART];
__device__ __half g_Wh[C_OUT * D_IN];   // [n][k] K-major fp16

// ---------------------------------------------------------------------------
// helpers
// ---------------------------------------------------------------------------
__device__ __forceinline__ u32 smem_u32(const void* p) {
    u32 a; asm("{ .reg .u64 t; cvta.to.shared.u64 t, %1; cvt.u32.u64 %0, t; }"
               : "=r"(a) : "l"(p));
    return a;
}
__device__ __forceinline__ void sts8(u32 addr, u32 a, u32 b) {
    asm volatile("st.shared.v2.u32 [%0], {%1,%2};" :: "r"(addr), "r"(a), "r"(b) : "memory");
}
__device__ __forceinline__ void sts64(u32 addr, u64 v) {
    asm volatile("st.shared.b64 [%0], %1;" :: "r"(addr), "l"(v) : "memory");
}
__device__ __forceinline__ void ldm_x4(u32 a, u32& r0, u32& r1, u32& r2, u32& r3) {
    asm volatile("ldmatrix.sync.aligned.m8n8.x4.shared.b16 {%0,%1,%2,%3}, [%4];"
                 : "=r"(r0), "=r"(r1), "=r"(r2), "=r"(r3) : "r"(a));
}
__device__ __forceinline__ void mma16816(float& c0, float& c1, float& c2, float& c3,
                                         u32 a0, u32 a1, u32 a2, u32 a3,
                                         u32 b0, u32 b1) {
    asm volatile("mma.sync.aligned.m16n8k16.row.col.f32.f16.f16.f32 "
                 "{%0,%1,%2,%3}, {%4,%5,%6,%7}, {%8,%9}, {%0,%1,%2,%3};"
                 : "+f"(c0), "+f"(c1), "+f"(c2), "+f"(c3)
                 : "r"(a0), "r"(a1), "r"(a2), "r"(a3), "r"(b0), "r"(b1));
}
// fp32x2 packed helpers
__device__ __forceinline__ u64 pk(float lo, float hi) {
    u64 r; asm("mov.b64 %0,{%1,%2};" : "=l"(r) : "f"(lo), "f"(hi)); return r;
}
__device__ __forceinline__ void upk(u64 v, float& lo, float& hi) {
    asm("mov.b64 {%0,%1},%2;" : "=f"(lo), "=f"(hi) : "l"(v));
}
__device__ __forceinline__ void fma2(u64& d, u64 a, u64 b) {
    asm("fma.rn.f32x2 %0,%1,%2,%0;" : "+l"(d) : "l"(a), "l"(b));
}
__device__ __forceinline__ u32 h2(float lo, float hi) {
    u32 r; asm("cvt.rn.f16x2.f32 %0, %1, %2;" : "=r"(r) : "f"(hi), "f"(lo)); return r;
}

// ---------------------------------------------------------------------------
// W convert prologue: g_Wh[n][k] = fp16(W[k][n])
// ---------------------------------------------------------------------------
__global__ void wconv_kernel(const float* __restrict__ W) {
    int idx = blockIdx.x * blockDim.x + threadIdx.x;
    if (idx >= D_IN * C_OUT) return;
    int k = idx / C_OUT, n = idx % C_OUT;
    g_Wh[n * D_IN + k] = __float2half_rn(W[idx]);
}

// ---------------------------------------------------------------------------
// Pass 1: X = relu(x@W + b) via single fp16 mma.sync.
// CTA: 128 rows x 128 cols; 8 warps, warp tile 32(m) x 64(n); 2 CTAs/SM.
// W (fp16, 4 K-chunks) staged once in smem; x double-buffered (fp16 at LDG).
// Epilogue: U->out[:,0:32], T->out[:,32:64], V/Z->smem, VtZ+colsums->g_part.
// ---------------------------------------------------------------------------
__global__ __launch_bounds__(THREADS, 2)
void pass1_kernel(const float* __restrict__ x, const float* __restrict__ b,
                  float* __restrict__ out, int N)
{
    extern __shared__ __align__(16) char dsm[];
    __shared__ float s_b[C_OUT];

    const int tid = threadIdx.x, lane = tid & 31, wid = tid >> 5;
    const int wm = wid & 3, wn = wid >> 2;     // warp tile coords
    const int r0 = blockIdx.x * TM;
    const u32 base = smem_u32(dsm);

    if (tid < C_OUT) s_b[tid] = b[tid];

    // ---- stage all of W (fp16, 4 chunks) into smem ----
#pragma unroll
    for (int q = 0; q < 32; q++) {
        int u = tid + 256 * q;                 // 8192 u64 units
        int n = u >> 6;                        // 0..127
        int kk = (u & 63) * 4;                 // 0..252
        int ch = kk >> 6, ko = kk & 63;
        sts64(base + ch * TILE_B + n * RB + ko * 2,
              *(const u64*)(g_Wh + n * D_IN + kk));
    }

    float acc[2][8][4];
#pragma unroll
    for (int mt = 0; mt < 2; mt++)
#pragma unroll
        for (int nt = 0; nt < 8; nt++)
#pragma unroll
            for (int q = 0; q < 4; q++) acc[mt][nt][q] = 0.f;

    u32 xh[16];   // 8 float4 -> 8 pairs of f16x2

    auto ldg = [&](int c) {
        const float* xp = x + (size_t)r0 * D_IN + c * KC;
#pragma unroll
        for (int q = 0; q < 8; q++) {
            int f = tid + 256 * q;                 // 2048 float4 slots
            int row = f >> 4, c4 = (f & 15) * 4;
            float4 v = make_float4(0.f, 0.f, 0.f, 0.f);
            if (r0 + row < N) v = *(const float4*)(xp + (size_t)row * D_IN + c4);
            xh[2 * q]     = h2(v.x, v.y);
            xh[2 * q + 1] = h2(v.z, v.w);
        }
    };
    auto sts = [&](u32 xbuf) {
        const u32 xb = base + XOFF + xbuf;
#pragma unroll
        for (int q = 0; q < 8; q++) {
            int f = tid + 256 * q;
            int row = f >> 4, c4 = (f & 15) * 4;
            sts8(xb + row * RB + c4 * 2, xh[2 * q], xh[2 * q + 1]);
        }
    };
    auto mma_chunk = [&](int c, u32 xbuf) {
        const u32 ab = base + XOFF + xbuf;
        const u32 bb = base + c * TILE_B;
        const u32 aoff = (wm * 32 + (lane & 15)) * RB + (lane >> 4) * 16;
        const u32 boff = (wn * 64 + (lane & 7) + ((lane >> 4) & 1) * 8) * RB
                       + ((lane >> 3) & 1) * 16;
#pragma unroll
        for (int ks = 0; ks < 4; ks++) {
            u32 a[2][4];
            ldm_x4(ab + aoff + ks * 32,           a[0][0], a[0][1], a[0][2], a[0][3]);
            ldm_x4(ab + aoff + 16 * RB + ks * 32, a[1][0], a[1][1], a[1][2], a[1][3]);
#pragma unroll
            for (int np = 0; np < 4; np++) {      // nt pair {2np, 2np+1}
                u32 b0, b1, b2, b3;
                ldm_x4(bb + boff + np * 16 * RB + ks * 32, b0, b1, b2, b3);
#pragma unroll
                for (int mt = 0; mt < 2; mt++) {
                    mma16816(acc[mt][2 * np][0], acc[mt][2 * np][1],
                             acc[mt][2 * np][2], acc[mt][2 * np][3],
                             a[mt][0], a[mt][1], a[mt][2], a[mt][3], b0, b1);
                    mma16816(acc[mt][2 * np + 1][0], acc[mt][2 * np + 1][1],
                             acc[mt][2 * np + 1][2], acc[mt][2 * np + 1][3],
                             a[mt][0], a[mt][1], a[mt][2], a[mt][3], b2, b3);
                }
            }
        }
    };

    // software pipeline over x chunks: LDG(c+1) || MMA(c)
    ldg(0);
    sts(0);
    __syncthreads();
#pragma unroll
    for (int c = 0; c < NCH; c++) {
        if (c < NCH - 1) ldg(c + 1);
        mma_chunk(c, (c & 1) * TILE_B);
        if (c < NCH - 1) sts(((c + 1) & 1) * TILE_B);
        __syncthreads();
    }

    // ---- epilogue (reuses smem; W/x no longer needed) ----
    float* vs   = (float*)dsm;              // [128][34]
    float* zs   = vs + 128 * 34;            // [128][34]
    float* redU = zs + 128 * 34;            // [4][32]
    float* redV = redU + 128;               // [4][32]

#pragma unroll
    for (int nt = 0; nt < 8; nt++) {
        const int colb = wn * 64 + nt * 8 + (lane & 3) * 2;
        const float b0 = s_b[colb], b1 = s_b[colb + 1];
        float v[2][4];
        int rl[2];
#pragma unroll
        for (int mt = 0; mt < 2; mt++) {
            rl[mt] = wm * 32 + mt * 16 + (lane >> 2);
            const bool ok1 = (r0 + rl[mt]) < N, ok2 = (r0 + rl[mt] + 8) < N;
            v[mt][0] = ok1 ? fmaxf(acc[mt][nt][0] + b0, 0.f) : 0.f;
            v[mt][1] = ok1 ? fmaxf(acc[mt][nt][1] + b1, 0.f) : 0.f;
            v[mt][2] = ok2 ? fmaxf(acc[mt][nt][2] + b0, 0.f) : 0.f;
            v[mt][3] = ok2 ? fmaxf(acc[mt][nt][3] + b1, 0.f) : 0.f;
        }
        if (wn == 0) {
            if (nt < 4) {
                // U -> out[:, colb] (cols 0..31)
#pragma unroll
                for (int mt = 0; mt < 2; mt++) {
                    if (r0 + rl[mt] < N)
                        *(float2*)(out + (size_t)(r0 + rl[mt]) * 64 + colb) =
                            make_float2(v[mt][0], v[mt][1]);
                    if (r0 + rl[mt] + 8 < N)
                        *(float2*)(out + (size_t)(r0 + rl[mt] + 8) * 64 + colb) =
                            make_float2(v[mt][2], v[mt][3]);
                }
                float s0 = v[0][0] + v[0][2] + v[1][0] + v[1][2];
                float s1 = v[0][1] + v[0][3] + v[1][1] + v[1][3];
                s0 += __shfl_down_sync(0xffffffffu, s0, 16);
                s0 += __shfl_down_sync(0xffffffffu, s0, 8);
                s0 += __shfl_down_sync(0xffffffffu, s0, 4);
                s1 += __shfl_down_sync(0xffffffffu, s1, 16);
                s1 += __shfl_down_sync(0xffffffffu, s1, 8);
                s1 += __shfl_down_sync(0xffffffffu, s1, 4);
                if (lane < 4) {
                    redU[wm * 32 + nt * 8 + lane * 2]     = s0;
                    redU[wm * 32 + nt * 8 + lane * 2 + 1] = s1;
                }
            } else {
                // V -> vs[:, colb-32]
                const int vc = colb - 32;
#pragma unroll
                for (int mt = 0; mt < 2; mt++) {
                    *(float2*)(vs + rl[mt] * 34 + vc)       = make_float2(v[mt][0], v[mt][1]);
                    *(float2*)(vs + (rl[mt] + 8) * 34 + vc) = make_float2(v[mt][2], v[mt][3]);
                }
                float s0 = v[0][0] + v[0][2] + v[1][0] + v[1][2];
                float s1 = v[0][1] + v[0][3] + v[1][1] + v[1][3];
                s0 += __shfl_down_sync(0xffffffffu, s0, 16);
                s0 += __shfl_down_sync(0xffffffffu, s0, 8);
                s0 += __shfl_down_sync(0xffffffffu, s0, 4);
                s1 += __shfl_down_sync(0xffffffffu, s1, 16);
                s1 += __shfl_down_sync(0xffffffffu, s1, 8);
                s1 += __shfl_down_sync(0xffffffffu, s1, 4);
                if (lane < 4) {
                    redV[wm * 32 + (nt - 4) * 8 + lane * 2]     = s0;
                    redV[wm * 32 + (nt - 4) * 8 + lane * 2 + 1] = s1;
                }
            }
        } else {
            if (nt < 4) {
                // Z -> zs[:, colb-64]
                const int zc = colb - 64;
#pragma unroll
                for (int mt = 0; mt < 2; mt++) {
                    *(float2*)(zs + rl[mt] * 34 + zc)       = make_float2(v[mt][0], v[mt][1]);
                    *(float2*)(zs + (rl[mt] + 8) * 34 + zc) = make_float2(v[mt][2], v[mt][3]);
                }
            } else {
                // T -> out[:, colb-64] (cols 32..63)
                const int tc = colb - 64;
#pragma unroll
                for (int mt = 0; mt < 2; mt++) {
                    if (r0 + rl[mt] < N)
                        *(float2*)(out + (size_t)(r0 + rl[mt]) * 64 + tc) =
                            make_float2(v[mt][0], v[mt][1]);
                    if (r0 + rl[mt] + 8 < N)
                        *(float2*)(out + (size_t)(r0 + rl[mt] + 8) * 64 + tc) =
                            make_float2(v[mt][2], v[mt][3]);
                }
            }
        }
    }
    __syncthreads();

    // ---- VtZ partials ----
    {
        const int i2 = tid >> 4, j2 = tid & 15;
        const int kk0 = 2 * i2, jj0 = 2 * j2;
        u64 a0 = 0ull, a1 = 0ull;
#pragma unroll 4
        for (int row = 0; row < 128; row++) {
            float v0 = vs[row * 34 + kk0];
            float v1 = vs[row * 34 + kk0 + 1];
            u64 zz = *(u64*)(zs + row * 34 + jj0);
            fma2(a0, pk(v0, v0), zz);
            fma2(a1, pk(v1, v1), zz);
        }
        float p00, p01, p10, p11;
        upk(a0, p00, p01); upk(a1, p10, p11);
        const int blk = blockIdx.x;
        g_part[(size_t)(kk0 * 32 + jj0)           * MAXB + blk] = p00;
        g_part[(size_t)(kk0 * 32 + jj0 + 1)       * MAXB + blk] = p01;
        g_part[(size_t)((kk0 + 1) * 32 + jj0)     * MAXB + blk] = p10;
        g_part[(size_t)((kk0 + 1) * 32 + jj0 + 1) * MAXB + blk] = p11;
    }
    // colsum partials
    if (tid < 32) {
        float s = redU[tid] + redU[32 + tid] + redU[64 + tid] + redU[96 + tid];
        g_part[(size_t)(1024 + tid) * MAXB + blockIdx.x] = s;
    } else if (tid < 64) {
        int t = tid - 32;
        float s = redV[t] + redV[32 + t] + redV[64 + t] + redV[96 + t];
        g_part[(size_t)(1056 + t) * MAXB + blockIdx.x] = s;
    }
}

// ---------------------------------------------------------------------------
// Pass 2: deterministic reduction (one warp per output, fixed shuffle tree)
// ---------------------------------------------------------------------------
__global__ void reduce_kernel(int nb)
{
    int gtid = blockIdx.x * blockDim.x + threadIdx.x;
    int warp = gtid >> 5, lane = gtid & 31;
    if (warp >= NPART) return;
    const float* p = g_part + (size_t)warp * MAXB;
    float s = 0.f;
    for (int bq = lane; bq < nb; bq += 32) s += p[bq];
#pragma unroll
    for (int off = 16; off; off >>= 1)
        s += __shfl_down_sync(0xffffffffu, s, off);
    if (lane == 0) g_red[warp] = s;
}

// ---------------------------------------------------------------------------
// Pass 3: out[:,0:32] = U @ (VtZ * D) in place.
// 2 rows per thread: one M LDS feeds both rows (halves LDS per row).
// ---------------------------------------------------------------------------
__global__ __launch_bounds__(THREADS)
void pass3_kernel(float* __restrict__ out, int N)
{
    __shared__ __align__(16) float M[32 * 34];
    __shared__ float sD;
    const int tid = threadIdx.x;

    if (tid < 32) {
        float p = g_red[1024 + tid] * g_red[1056 + tid];
#pragma unroll
        for (int off = 16; off; off >>= 1)
            p += __shfl_down_sync(0xffffffffu, p, off);
        if (tid == 0) sD = 1.0f / (p / (float)N + EPSV);
    }
    __syncthreads();
    const float D = sD;
#pragma unroll
    for (int q = tid; q < 1024; q += THREADS) {
        int k = q >> 5, c = q & 31;
        M[k * 34 + c] = g_red[q] * D;
    }
    __syncthreads();

    const int rowA = blockIdx.x * (2 * THREADS) + tid;
    const int rowB = rowA + THREADS;
    const bool okA = rowA < N, okB = rowB < N;

    float uA[32], uB[32];
#pragma unroll
    for (int t = 0; t < 8; t++) {
        ((float4*)uA)[t] = okA ? *(const float4*)(out + (size_t)rowA * 64 + 4 * t)
                               : make_float4(0.f, 0.f, 0.f, 0.f);
        ((float4*)uB)[t] = okB ? *(const float4*)(out + (size_t)rowB * 64 + 4 * t)
                               : make_float4(0.f, 0.f, 0.f, 0.f);
    }

    u64 accA[16], accB[16];
#pragma unroll
    for (int c = 0; c < 16; c++) { accA[c] = 0ull; accB[c] = 0ull; }
#pragma unroll
    for (int k = 0; k < 32; k++) {
        u64 a = pk(uA[k], uA[k]);
        u64 b = pk(uB[k], uB[k]);
#pragma unroll
        for (int c = 0; c < 16; c++) {
            u64 m = *(u64*)(M + k * 34 + 2 * c);
            fma2(accA[c], a, m);
            fma2(accB[c], b, m);
        }
    }
#pragma unroll
    for (int c = 0; c < 8; c++) {
        float r0, r1, r2, r3;
        if (okA) {
            upk(accA[2 * c], r0, r1); upk(accA[2 * c + 1], r2, r3);
            *(float4*)(out + (size_t)rowA * 64 + 4 * c) = make_float4(r0, r1, r2, r3);
        }
        if (okB) {
            upk(accB[2 * c], r0, r1); upk(accB[2 * c + 1], r2, r3);
            *(float4*)(out + (size_t)rowB * 64 + 4 * c) = make_float4(r0, r1, r2, r3);
        }
    }
}

// ---------------------------------------------------------------------------
extern "C" void kernel_launch(void* const* d_in, const int* in_sizes, int n_in,
                              void* d_out, int out_size)
{
    const float* x = (const float*)d_in[0];
    const float* W = (const float*)d_in[1];
    const float* b = (const float*)d_in[2];
    float* out = (float*)d_out;

    const int N  = in_sizes[0] / D_IN;
    const int nb = (N + TM - 1) / TM;

    cudaFuncSetAttribute(pass1_kernel,
                         cudaFuncAttributeMaxDynamicSharedMemorySize, DSM_B);

    wconv_kernel<<<(D_IN * C_OUT + 255) / 256, 256>>>(W);
    pass1_kernel<<<nb, THREADS, DSM_B>>>(x, b, out, N);
    reduce_kernel<<<(NPART * 32 + THREADS - 1) / THREADS, THREADS>>>(nb);
    pass3_kernel<<<(N + 2 * THREADS - 1) / (2 * THREADS), THREADS>>>(out, N);
}

// round 6
// speedup vs baseline: 2.7991x; 1.1631x over previous
#include <cuda_runtime.h>
#include <cuda_fp16.h>
#include <cstdint>

typedef unsigned int u32;
typedef unsigned long long u64;

// Problem constants (x[N,256], W[256,128], b[128], out[N,64])
#define D_IN   256
#define C_OUT  128
#define EPSV   1e-6f
#define TM     128
#define THREADS 256
#define MAXB   4096
#define NPART  1088          // 1024 VtZ + 32 sumU + 32 sumV
#define KC     64            // K elems per chunk
#define NCH    4             // 256 / 64
#define GRIDP  296           // persistent grid: 2 CTAs x 148 SMs

// fp16 tile 128 x 64, padded row stride 72 elems (144 B) -> conflict-free ldmatrix
#define AST      72
#define RB       (AST * 2)           // row bytes = 144
#define TILE_B   (128 * RB)          // 18432 B
#define XOFF     (4 * TILE_B)        // W: 4 chunks staged once per CTA
#define DSM_B    (XOFF + 2 * TILE_B) // 110592 B -> 2 CTAs/SM

__device__ float g_part[(size_t)NPART * MAXB];
__device__ float g_red[NPART];
__device__ __half g_Wh[C_OUT * D_IN];   // [n][k] K-major fp16

// ---------------------------------------------------------------------------
// helpers
// ---------------------------------------------------------------------------
__device__ __forceinline__ u32 smem_u32(const void* p) {
    u32 a; asm("{ .reg .u64 t; cvta.to.shared.u64 t, %1; cvt.u32.u64 %0, t; }"
               : "=r"(a) : "l"(p));
    return a;
}
__device__ __forceinline__ void sts8(u32 addr, u32 a, u32 b) {
    asm volatile("st.shared.v2.u32 [%0], {%1,%2};" :: "r"(addr), "r"(a), "r"(b) : "memory");
}
__device__ __forceinline__ void sts16(u32 addr, float4 v) {
    asm volatile("st.shared.v4.b32 [%0], {%1,%2,%3,%4};"
                 :: "r"(addr), "f"(v.x), "f"(v.y), "f"(v.z), "f"(v.w) : "memory");
}
__device__ __forceinline__ void ldm_x4(u32 a, u32& r0, u32& r1, u32& r2, u32& r3) {
    asm volatile("ldmatrix.sync.aligned.m8n8.x4.shared.b16 {%0,%1,%2,%3}, [%4];"
                 : "=r"(r0), "=r"(r1), "=r"(r2), "=r"(r3) : "r"(a));
}
__device__ __forceinline__ void mma16816(float& c0, float& c1, float& c2, float& c3,
                                         u32 a0, u32 a1, u32 a2, u32 a3,
                                         u32 b0, u32 b1) {
    asm volatile("mma.sync.aligned.m16n8k16.row.col.f32.f16.f16.f32 "
                 "{%0,%1,%2,%3}, {%4,%5,%6,%7}, {%8,%9}, {%0,%1,%2,%3};"
                 : "+f"(c0), "+f"(c1), "+f"(c2), "+f"(c3)
                 : "r"(a0), "r"(a1), "r"(a2), "r"(a3), "r"(b0), "r"(b1));
}
// fp32x2 packed helpers
__device__ __forceinline__ u64 pk(float lo, float hi) {
    u64 r; asm("mov.b64 %0,{%1,%2};" : "=l"(r) : "f"(lo), "f"(hi)); return r;
}
__device__ __forceinline__ void upk(u64 v, float& lo, float& hi) {
    asm("mov.b64 {%0,%1},%2;" : "=f"(lo), "=f"(hi) : "l"(v));
}
__device__ __forceinline__ void fma2(u64& d, u64 a, u64 b) {
    asm("fma.rn.f32x2 %0,%1,%2,%0;" : "+l"(d) : "l"(a), "l"(b));
}
__device__ __forceinline__ u32 h2(float lo, float hi) {
    u32 r; asm("cvt.rn.f16x2.f32 %0, %1, %2;" : "=r"(r) : "f"(hi), "f"(lo)); return r;
}

// ---------------------------------------------------------------------------
// W convert prologue: g_Wh[n][k] = fp16(W[k][n])
// ---------------------------------------------------------------------------
__global__ void wconv_kernel(const float* __restrict__ W) {
    int idx = blockIdx.x * blockDim.x + threadIdx.x;
    if (idx >= D_IN * C_OUT) return;
    int k = idx / C_OUT, n = idx % C_OUT;
    g_Wh[n * D_IN + k] = __float2half_rn(W[idx]);
}

// ---------------------------------------------------------------------------
// Pass 1 (persistent): X = relu(x@W + b) via fp16 mma.sync.
// 296 CTAs, each loops over row-tiles. W staged ONCE per CTA (fp16, 72 KB);
// x double-buffered; next tile's chunk-0 LDG overlapped with the epilogue.
// Epilogue: U->out[:,0:32], T->out[:,32:64], VtZ + colsums -> g_part[tile].
// ---------------------------------------------------------------------------
__global__ __launch_bounds__(THREADS, 2)
void pass1_kernel(const float* __restrict__ x, const float* __restrict__ b,
                  float* __restrict__ out, int N, int nb)
{
    extern __shared__ __align__(16) char dsm[];
    __shared__ float s_b[C_OUT];
    __shared__ float redU[128], redV[128];

    const int tid = threadIdx.x, lane = tid & 31, wid = tid >> 5;
    const int wm = wid & 3, wn = wid >> 2;     // warp tile coords
    const u32 base = smem_u32(dsm);

    if (tid < C_OUT) s_b[tid] = b[tid];

    // ---- stage all of W (fp16, 4 chunks) once: 16 LDG.128/STS.128 per thread
#pragma unroll
    for (int q = 0; q < 16; q++) {
        int f = tid + 256 * q;                 // 4096 float4 units
        int n = f >> 5;                        // 0..127
        int unit = f & 31;                     // 32 x 16B per n-row
        int ch = unit >> 3, ko = (unit & 7) * 8;
        float4 v = *(const float4*)(g_Wh + n * D_IN + unit * 8);
        sts16(base + ch * TILE_B + n * RB + ko * 2, v);
    }

    // epilogue scratch lives in the x-buffer region (W stays resident)
    float* vs = (float*)(dsm + XOFF);       // [128][34]
    float* zs = vs + 128 * 34;              // [128][34]

    u32 xh[16];   // 8 float4 -> 16 f16x2

    auto ldg = [&](int r0, int c) {
        const float* xp = x + (size_t)r0 * D_IN + c * KC;
#pragma unroll
        for (int q = 0; q < 8; q++) {
            int f = tid + 256 * q;                 // 2048 float4 slots
            int row = f >> 4, c4 = (f & 15) * 4;
            float4 v = make_float4(0.f, 0.f, 0.f, 0.f);
            if (r0 + row < N) v = *(const float4*)(xp + (size_t)row * D_IN + c4);
            xh[2 * q]     = h2(v.x, v.y);
            xh[2 * q + 1] = h2(v.z, v.w);
        }
    };
    auto sts = [&](u32 xbuf) {
        const u32 xb = base + XOFF + xbuf;
#pragma unroll
        for (int q = 0; q < 8; q++) {
            int f = tid + 256 * q;
            int row = f >> 4, c4 = (f & 15) * 4;
            sts8(xb + row * RB + c4 * 2, xh[2 * q], xh[2 * q + 1]);
        }
    };

    float acc[2][8][4];

    auto mma_chunk = [&](int c, u32 xbuf) {
        const u32 ab = base + XOFF + xbuf;
        const u32 bb = base + c * TILE_B;
        const u32 aoff = (wm * 32 + (lane & 15)) * RB + (lane >> 4) * 16;
        const u32 boff = (wn * 64 + (lane & 7) + ((lane >> 4) & 1) * 8) * RB
                       + ((lane >> 3) & 1) * 16;
#pragma unroll
        for (int ks = 0; ks < 4; ks++) {
            u32 a[2][4];
            ldm_x4(ab + aoff + ks * 32,           a[0][0], a[0][1], a[0][2], a[0][3]);
            ldm_x4(ab + aoff + 16 * RB + ks * 32, a[1][0], a[1][1], a[1][2], a[1][3]);
#pragma unroll
            for (int np = 0; np < 4; np++) {      // nt pair {2np, 2np+1}
                u32 b0, b1, b2, b3;
                ldm_x4(bb + boff + np * 16 * RB + ks * 32, b0, b1, b2, b3);
#pragma unroll
                for (int mt = 0; mt < 2; mt++) {
                    mma16816(acc[mt][2 * np][0], acc[mt][2 * np][1],
                             acc[mt][2 * np][2], acc[mt][2 * np][3],
                             a[mt][0], a[mt][1], a[mt][2], a[mt][3], b0, b1);
                    mma16816(acc[mt][2 * np + 1][0], acc[mt][2 * np + 1][1],
                             acc[mt][2 * np + 1][2], acc[mt][2 * np + 1][3],
                             a[mt][0], a[mt][1], a[mt][2], a[mt][3], b2, b3);
                }
            }
        }
    };

    // prefetch chunk 0 of first tile (overlaps with W staging latency)
    if ((int)blockIdx.x < nb) ldg(blockIdx.x * TM, 0);

    for (int tile = blockIdx.x; tile < nb; tile += GRIDP) {
        const int r0 = tile * TM;

#pragma unroll
        for (int mt = 0; mt < 2; mt++)
#pragma unroll
            for (int nt = 0; nt < 8; nt++)
#pragma unroll
                for (int q = 0; q < 4; q++) acc[mt][nt][q] = 0.f;

        sts(0);
        __syncthreads();
#pragma unroll
        for (int c = 0; c < NCH; c++) {
            if (c < NCH - 1) ldg(r0, c + 1);
            mma_chunk(c, (c & 1) * TILE_B);
            if (c < NCH - 1) sts(((c + 1) & 1) * TILE_B);
            __syncthreads();
        }

        // prefetch next tile's chunk 0 behind the epilogue
        if (tile + GRIDP < nb) ldg((tile + GRIDP) * TM, 0);

        // ---- epilogue ----
#pragma unroll
        for (int nt = 0; nt < 8; nt++) {
            const int colb = wn * 64 + nt * 8 + (lane & 3) * 2;
            const float b0 = s_b[colb], b1 = s_b[colb + 1];
            float v[2][4];
            int rl[2];
#pragma unroll
            for (int mt = 0; mt < 2; mt++) {
                rl[mt] = wm * 32 + mt * 16 + (lane >> 2);
                const bool ok1 = (r0 + rl[mt]) < N, ok2 = (r0 + rl[mt] + 8) < N;
                v[mt][0] = ok1 ? fmaxf(acc[mt][nt][0] + b0, 0.f) : 0.f;
                v[mt][1] = ok1 ? fmaxf(acc[mt][nt][1] + b1, 0.f) : 0.f;
                v[mt][2] = ok2 ? fmaxf(acc[mt][nt][2] + b0, 0.f) : 0.f;
                v[mt][3] = ok2 ? fmaxf(acc[mt][nt][3] + b1, 0.f) : 0.f;
            }
            if (wn == 0) {
                if (nt < 4) {
                    // U -> out[:, colb] (cols 0..31)
#pragma unroll
                    for (int mt = 0; mt < 2; mt++) {
                        if (r0 + rl[mt] < N)
                            *(float2*)(out + (size_t)(r0 + rl[mt]) * 64 + colb) =
                                make_float2(v[mt][0], v[mt][1]);
                        if (r0 + rl[mt] + 8 < N)
                            *(float2*)(out + (size_t)(r0 + rl[mt] + 8) * 64 + colb) =
                                make_float2(v[mt][2], v[mt][3]);
                    }
                    float s0 = v[0][0] + v[0][2] + v[1][0] + v[1][2];
                    float s1 = v[0][1] + v[0][3] + v[1][1] + v[1][3];
                    s0 += __shfl_down_sync(0xffffffffu, s0, 16);
                    s0 += __shfl_down_sync(0xffffffffu, s0, 8);
                    s0 += __shfl_down_sync(0xffffffffu, s0, 4);
                    s1 += __shfl_down_sync(0xffffffffu, s1, 16);
                    s1 += __shfl_down_sync(0xffffffffu, s1, 8);
                    s1 += __shfl_down_sync(0xffffffffu, s1, 4);
                    if (lane < 4) {
                        redU[wm * 32 + nt * 8 + lane * 2]     = s0;
                        redU[wm * 32 + nt * 8 + lane * 2 + 1] = s1;
                    }
                } else {
                    // V -> vs[:, colb-32]
                    const int vc = colb - 32;
#pragma unroll
                    for (int mt = 0; mt < 2; mt++) {
                        *(float2*)(vs + rl[mt] * 34 + vc)       = make_float2(v[mt][0], v[mt][1]);
                        *(float2*)(vs + (rl[mt] + 8) * 34 + vc) = make_float2(v[mt][2], v[mt][3]);
                    }
                    float s0 = v[0][0] + v[0][2] + v[1][0] + v[1][2];
                    float s1 = v[0][1] + v[0][3] + v[1][1] + v[1][3];
                    s0 += __shfl_down_sync(0xffffffffu, s0, 16);
                    s0 += __shfl_down_sync(0xffffffffu, s0, 8);
                    s0 += __shfl_down_sync(0xffffffffu, s0, 4);
                    s1 += __shfl_down_sync(0xffffffffu, s1, 16);
                    s1 += __shfl_down_sync(0xffffffffu, s1, 8);
                    s1 += __shfl_down_sync(0xffffffffu, s1, 4);
                    if (lane < 4) {
                        redV[wm * 32 + (nt - 4) * 8 + lane * 2]     = s0;
                        redV[wm * 32 + (nt - 4) * 8 + lane * 2 + 1] = s1;
                    }
                }
            } else {
                if (nt < 4) {
                    // Z -> zs[:, colb-64]
                    const int zc = colb - 64;
#pragma unroll
                    for (int mt = 0; mt < 2; mt++) {
                        *(float2*)(zs + rl[mt] * 34 + zc)       = make_float2(v[mt][0], v[mt][1]);
                        *(float2*)(zs + (rl[mt] + 8) * 34 + zc) = make_float2(v[mt][2], v[mt][3]);
                    }
                } else {
                    // T -> out[:, colb-64] (cols 32..63)
                    const int tc = colb - 64;
#pragma unroll
                    for (int mt = 0; mt < 2; mt++) {
                        if (r0 + rl[mt] < N)
                            *(float2*)(out + (size_t)(r0 + rl[mt]) * 64 + tc) =
                                make_float2(v[mt][0], v[mt][1]);
                        if (r0 + rl[mt] + 8 < N)
                            *(float2*)(out + (size_t)(r0 + rl[mt] + 8) * 64 + tc) =
                                make_float2(v[mt][2], v[mt][3]);
                    }
                }
            }
        }
        __syncthreads();

        // ---- VtZ partials ----
        {
            const int i2 = tid >> 4, j2 = tid & 15;
            const int kk0 = 2 * i2, jj0 = 2 * j2;
            u64 a0 = 0ull, a1 = 0ull;
#pragma unroll 4
            for (int row = 0; row < 128; row++) {
                float v0 = vs[row * 34 + kk0];
                float v1 = vs[row * 34 + kk0 + 1];
                u64 zz = *(u64*)(zs + row * 34 + jj0);
                fma2(a0, pk(v0, v0), zz);
                fma2(a1, pk(v1, v1), zz);
            }
            float p00, p01, p10, p11;
            upk(a0, p00, p01); upk(a1, p10, p11);
            g_part[(size_t)(kk0 * 32 + jj0)           * MAXB + tile] = p00;
            g_part[(size_t)(kk0 * 32 + jj0 + 1)       * MAXB + tile] = p01;
            g_part[(size_t)((kk0 + 1) * 32 + jj0)     * MAXB + tile] = p10;
            g_part[(size_t)((kk0 + 1) * 32 + jj0 + 1) * MAXB + tile] = p11;
        }
        // colsum partials
        if (tid < 32) {
            float s = redU[tid] + redU[32 + tid] + redU[64 + tid] + redU[96 + tid];
            g_part[(size_t)(1024 + tid) * MAXB + tile] = s;
        } else if (tid < 64) {
            int t = tid - 32;
            float s = redV[t] + redV[32 + t] + redV[64 + t] + redV[96 + t];
            g_part[(size_t)(1056 + t) * MAXB + tile] = s;
        }
        __syncthreads();   // vs/zs reads done before next tile's sts(0)
    }
}

// ---------------------------------------------------------------------------
// Pass 2: deterministic reduction (one warp per output, fixed shuffle tree)
// ---------------------------------------------------------------------------
__global__ void reduce_kernel(int nb)
{
    int gtid = blockIdx.x * blockDim.x + threadIdx.x;
    int warp = gtid >> 5, lane = gtid & 31;
    if (warp >= NPART) return;
    const float* p = g_part + (size_t)warp * MAXB;
    float s = 0.f;
    for (int bq = lane; bq < nb; bq += 32) s += p[bq];
#pragma unroll
    for (int off = 16; off; off >>= 1)
        s += __shfl_down_sync(0xffffffffu, s, off);
    if (lane == 0) g_red[warp] = s;
}

// ---------------------------------------------------------------------------
// Pass 3: out[:,0:32] = U @ (VtZ * D) in place.
// 2 rows/thread; M stride 36 -> LDS.128 (8 loads per k, 16B aligned).
// ---------------------------------------------------------------------------
__global__ __launch_bounds__(THREADS)
void pass3_kernel(float* __restrict__ out, int N)
{
    __shared__ __align__(16) float M[32 * 36];
    __shared__ float sD;
    const int tid = threadIdx.x;

    if (tid < 32) {
        float p = g_red[1024 + tid] * g_red[1056 + tid];
#pragma unroll
        for (int off = 16; off; off >>= 1)
            p += __shfl_down_sync(0xffffffffu, p, off);
        if (tid == 0) sD = 1.0f / (p / (float)N + EPSV);
    }
    __syncthreads();
    const float D = sD;
#pragma unroll
    for (int q = tid; q < 1024; q += THREADS) {
        int k = q >> 5, c = q & 31;
        M[k * 36 + c] = g_red[q] * D;
    }
    __syncthreads();

    const int rowA = blockIdx.x * (2 * THREADS) + tid;
    const int rowB = rowA + THREADS;
    const bool okA = rowA < N, okB = rowB < N;

    float uA[32], uB[32];
#pragma unroll
    for (int t = 0; t < 8; t++) {
        ((float4*)uA)[t] = okA ? *(const float4*)(out + (size_t)rowA * 64 + 4 * t)
                               : make_float4(0.f, 0.f, 0.f, 0.f);
        ((float4*)uB)[t] = okB ? *(const float4*)(out + (size_t)rowB * 64 + 4 * t)
                               : make_float4(0.f, 0.f, 0.f, 0.f);
    }

    u64 accA[16], accB[16];
#pragma unroll
    for (int c = 0; c < 16; c++) { accA[c] = 0ull; accB[c] = 0ull; }
#pragma unroll
    for (int k = 0; k < 32; k++) {
        u64 a = pk(uA[k], uA[k]);
        u64 b = pk(uB[k], uB[k]);
#pragma unroll
        for (int cq = 0; cq < 8; cq++) {
            float4 m = *(float4*)(M + k * 36 + 4 * cq);
            u64 m0 = pk(m.x, m.y), m1 = pk(m.z, m.w);
            fma2(accA[2 * cq], a, m0);
            fma2(accA[2 * cq + 1], a, m1);
            fma2(accB[2 * cq], b, m0);
            fma2(accB[2 * cq + 1], b, m1);
        }
    }
#pragma unroll
    for (int c = 0; c < 8; c++) {
        float r0, r1, r2, r3;
        if (okA) {
            upk(accA[2 * c], r0, r1); upk(accA[2 * c + 1], r2, r3);
            *(float4*)(out + (size_t)rowA * 64 + 4 * c) = make_float4(r0, r1, r2, r3);
        }
        if (okB) {
            upk(accB[2 * c], r0, r1); upk(accB[2 * c + 1], r2, r3);
            *(float4*)(out + (size_t)rowB * 64 + 4 * c) = make_float4(r0, r1, r2, r3);
        }
    }
}

// ---------------------------------------------------------------------------
extern "C" void kernel_launch(void* const* d_in, const int* in_sizes, int n_in,
                              void* d_out, int out_size)
{
    const float* x = (const float*)d_in[0];
    const float* W = (const float*)d_in[1];
    const float* b = (const float*)d_in[2];
    float* out = (float*)d_out;

    const int N  = in_sizes[0] / D_IN;
    const int nb = (N + TM - 1) / TM;
    const int np = nb < GRIDP ? nb : GRIDP;

    cudaFuncSetAttribute(pass1_kernel,
                         cudaFuncAttributeMaxDynamicSharedMemorySize, DSM_B);

    wconv_kernel<<<(D_IN * C_OUT + 255) / 256, 256>>>(W);
    pass1_kernel<<<np, THREADS, DSM_B>>>(x, b, out, N, nb);
    reduce_kernel<<<(NPART * 32 + THREADS - 1) / THREADS, THREADS>>>(nb);
    pass3_kernel<<<(N + 2 * THREADS - 1) / (2 * THREADS), THREADS>>>(out, N);
}

// round 7
// speedup vs baseline: 2.8132x; 1.0050x over previous
#include <cuda_runtime.h>
#include <cuda_fp16.h>
#include <cstdint>

typedef unsigned int u32;
typedef unsigned long long u64;

// Problem constants (x[N,256], W[256,128], b[128], out[N,64])
#define D_IN   256
#define C_OUT  128
#define EPSV   1e-6f
#define TM     128
#define THREADS 256
#define MAXB   4096
#define NPART  1088          // 1024 VtZ + 32 sumU + 32 sumV
#define GRIDP  296           // persistent grid: 2 CTAs x 148 SMs

// fp16 W tile 128 x 64, padded row stride 72 elems (144 B): conflict-free ldmatrix
#define AST      72
#define RB       (AST * 2)           // row bytes = 144
#define TILE_B   (128 * RB)          // 18432 B
#define XOFF     (4 * TILE_B)        // W: 4 chunks resident per CTA (73728 B)
#define DSM_B    (XOFF + 2 * 128 * 34 * 4)  // + vs/zs scratch = 108544 B

__device__ float g_part[(size_t)NPART * MAXB];
__device__ float g_red[NPART];
__device__ __half g_Wh[C_OUT * D_IN];   // [n][k] K-major fp16

// ---------------------------------------------------------------------------
// helpers
// ---------------------------------------------------------------------------
__device__ __forceinline__ u32 smem_u32(const void* p) {
    u32 a; asm("{ .reg .u64 t; cvta.to.shared.u64 t, %1; cvt.u32.u64 %0, t; }"
               : "=r"(a) : "l"(p));
    return a;
}
__device__ __forceinline__ void sts16(u32 addr, float4 v) {
    asm volatile("st.shared.v4.b32 [%0], {%1,%2,%3,%4};"
                 :: "r"(addr), "f"(v.x), "f"(v.y), "f"(v.z), "f"(v.w) : "memory");
}
__device__ __forceinline__ void ldm_x4(u32 a, u32& r0, u32& r1, u32& r2, u32& r3) {
    asm volatile("ldmatrix.sync.aligned.m8n8.x4.shared.b16 {%0,%1,%2,%3}, [%4];"
                 : "=r"(r0), "=r"(r1), "=r"(r2), "=r"(r3) : "r"(a));
}
__device__ __forceinline__ void mma16816(float& c0, float& c1, float& c2, float& c3,
                                         u32 a0, u32 a1, u32 a2, u32 a3,
                                         u32 b0, u32 b1) {
    asm volatile("mma.sync.aligned.m16n8k16.row.col.f32.f16.f16.f32 "
                 "{%0,%1,%2,%3}, {%4,%5,%6,%7}, {%8,%9}, {%0,%1,%2,%3};"
                 : "+f"(c0), "+f"(c1), "+f"(c2), "+f"(c3)
                 : "r"(a0), "r"(a1), "r"(a2), "r"(a3), "r"(b0), "r"(b1));
}
// fp32x2 packed helpers
__device__ __forceinline__ u64 pk(float lo, float hi) {
    u64 r; asm("mov.b64 %0,{%1,%2};" : "=l"(r) : "f"(lo), "f"(hi)); return r;
}
__device__ __forceinline__ void upk(u64 v, float& lo, float& hi) {
    asm("mov.b64 {%0,%1},%2;" : "=f"(lo), "=f"(hi) : "l"(v));
}
__device__ __forceinline__ void fma2(u64& d, u64 a, u64 b) {
    asm("fma.rn.f32x2 %0,%1,%2,%0;" : "+l"(d) : "l"(a), "l"(b));
}
__device__ __forceinline__ u32 h2(float lo, float hi) {
    u32 r; asm("cvt.rn.f16x2.f32 %0, %1, %2;" : "=r"(r) : "f"(hi), "f"(lo)); return r;
}

// ---------------------------------------------------------------------------
// W convert prologue: g_Wh[n][k] = fp16(W[k][n])
// ---------------------------------------------------------------------------
__global__ void wconv_kernel(const float* __restrict__ W) {
    int idx = blockIdx.x * blockDim.x + threadIdx.x;
    if (idx >= D_IN * C_OUT) return;
    int k = idx / C_OUT, n = idx % C_OUT;
    g_Wh[n * D_IN + k] = __float2half_rn(W[idx]);
}

// ---------------------------------------------------------------------------
// Pass 1 (persistent, sync-free mainloop):
// X = relu(x@W + b) via fp16 mma.sync. Warp tile 16(m) x 128(n): A fragments
// loaded DIRECTLY from gmem (4 x LDG.64 per k16 step, in-register fp16 cvt),
// W resident in smem (B via ldmatrix). Zero barriers in the mainloop.
// Epilogue: U->out[:,0:32], T->out[:,32:64], V/Z->smem, VtZ+colsums->g_part.
// ---------------------------------------------------------------------------
__global__ __launch_bounds__(THREADS, 2)
void pass1_kernel(const float* __restrict__ x, const float* __restrict__ b,
                  float* __restrict__ out, int N, int nb)
{
    extern __shared__ __align__(16) char dsm[];
    __shared__ float s_b[C_OUT];
    __shared__ float redU[256], redV[256];     // [8 warps][32 cols]

    const int tid = threadIdx.x, lane = tid & 31, wid = tid >> 5;
    const u32 base = smem_u32(dsm);

    if (tid < C_OUT) s_b[tid] = b[tid];

    // ---- stage all of W (fp16, 4 chunks) once ----
#pragma unroll
    for (int q = 0; q < 16; q++) {
        int f = tid + 256 * q;                 // 4096 float4 units
        int n = f >> 5;
        int unit = f & 31;
        int ch = unit >> 3, ko = (unit & 7) * 8;
        float4 v = *(const float4*)(g_Wh + n * D_IN + unit * 8);
        sts16(base + ch * TILE_B + n * RB + ko * 2, v);
    }
    __syncthreads();

    float* vs = (float*)(dsm + XOFF);       // [128][34]
    float* zs = vs + 128 * 34;              // [128][34]

    const int wrow = wid * 16 + (lane >> 2);          // 0..127 (CTA-relative)
    const u32 boffb = (u32)(((lane & 7) + ((lane >> 4) & 1) * 8) * RB
                            + ((lane >> 3) & 1) * 16);

    float acc[16][4];
    float2 bA[2][4];
    const float2 z2 = make_float2(0.f, 0.f);

    for (int tile = blockIdx.x; tile < nb; tile += GRIDP) {
        const int r0 = tile * TM;
        const bool ok1 = (r0 + wrow) < N, ok2 = (r0 + wrow + 8) < N;
        const float* xr = x + (size_t)(r0 + wrow) * D_IN + (lane & 3) * 2;

#pragma unroll
        for (int nf = 0; nf < 16; nf++)
#pragma unroll
            for (int q = 0; q < 4; q++) acc[nf][q] = 0.f;

        // prologue: k-steps 0,1 in flight
#pragma unroll
        for (int p = 0; p < 2; p++) {
            const float* xk = xr + p * 16;
            bA[p][0] = ok1 ? *(const float2*)(xk)                : z2;
            bA[p][1] = ok2 ? *(const float2*)(xk + 8 * D_IN)     : z2;
            bA[p][2] = ok1 ? *(const float2*)(xk + 8)            : z2;
            bA[p][3] = ok2 ? *(const float2*)(xk + 8 * D_IN + 8) : z2;
        }

#pragma unroll
        for (int ks = 0; ks < 16; ks++) {
            const int p = ks & 1;
            u32 af0 = h2(bA[p][0].x, bA[p][0].y);
            u32 af1 = h2(bA[p][1].x, bA[p][1].y);
            u32 af2 = h2(bA[p][2].x, bA[p][2].y);
            u32 af3 = h2(bA[p][3].x, bA[p][3].y);
            if (ks < 14) {
                const float* xk = xr + (ks + 2) * 16;
                bA[p][0] = ok1 ? *(const float2*)(xk)                : z2;
                bA[p][1] = ok2 ? *(const float2*)(xk + 8 * D_IN)     : z2;
                bA[p][2] = ok1 ? *(const float2*)(xk + 8)            : z2;
                bA[p][3] = ok2 ? *(const float2*)(xk + 8 * D_IN + 8) : z2;
            }
            const u32 bb = base + (ks >> 2) * TILE_B + boffb + (ks & 3) * 32;
#pragma unroll
            for (int np = 0; np < 8; np++) {
                u32 b0, b1, b2, b3;
                ldm_x4(bb + np * 16 * RB, b0, b1, b2, b3);
                mma16816(acc[2 * np][0], acc[2 * np][1], acc[2 * np][2], acc[2 * np][3],
                         af0, af1, af2, af3, b0, b1);
                mma16816(acc[2 * np + 1][0], acc[2 * np + 1][1],
                         acc[2 * np + 1][2], acc[2 * np + 1][3],
                         af0, af1, af2, af3, b2, b3);
            }
        }

        // ---- epilogue ----
#pragma unroll
        for (int nf = 0; nf < 16; nf++) {
            const int col = nf * 8 + (lane & 3) * 2;
            const float b0 = s_b[col], b1 = s_b[col + 1];
            float v0 = ok1 ? fmaxf(acc[nf][0] + b0, 0.f) : 0.f;
            float v1 = ok1 ? fmaxf(acc[nf][1] + b1, 0.f) : 0.f;
            float v2 = ok2 ? fmaxf(acc[nf][2] + b0, 0.f) : 0.f;
            float v3 = ok2 ? fmaxf(acc[nf][3] + b1, 0.f) : 0.f;

            if (nf < 4) {
                // U -> out cols 0..31
                if (ok1) *(float2*)(out + (size_t)(r0 + wrow) * 64 + col) =
                    make_float2(v0, v1);
                if (ok2) *(float2*)(out + (size_t)(r0 + wrow + 8) * 64 + col) =
                    make_float2(v2, v3);
                float s0 = v0 + v2, s1 = v1 + v3;
                s0 += __shfl_down_sync(0xffffffffu, s0, 16);
                s0 += __shfl_down_sync(0xffffffffu, s0, 8);
                s0 += __shfl_down_sync(0xffffffffu, s0, 4);
                s1 += __shfl_down_sync(0xffffffffu, s1, 16);
                s1 += __shfl_down_sync(0xffffffffu, s1, 8);
                s1 += __shfl_down_sync(0xffffffffu, s1, 4);
                if (lane < 4) {
                    redU[wid * 32 + nf * 8 + lane * 2]     = s0;
                    redU[wid * 32 + nf * 8 + lane * 2 + 1] = s1;
                }
            } else if (nf < 8) {
                // V -> vs (cols 0..31 of V)
                const int vc = col - 32;
                *(float2*)(vs + wrow * 34 + vc)       = make_float2(v0, v1);
                *(float2*)(vs + (wrow + 8) * 34 + vc) = make_float2(v2, v3);
                float s0 = v0 + v2, s1 = v1 + v3;
                s0 += __shfl_down_sync(0xffffffffu, s0, 16);
                s0 += __shfl_down_sync(0xffffffffu, s0, 8);
                s0 += __shfl_down_sync(0xffffffffu, s0, 4);
                s1 += __shfl_down_sync(0xffffffffu, s1, 16);
                s1 += __shfl_down_sync(0xffffffffu, s1, 8);
                s1 += __shfl_down_sync(0xffffffffu, s1, 4);
                if (lane < 4) {
                    redV[wid * 32 + (nf - 4) * 8 + lane * 2]     = s0;
                    redV[wid * 32 + (nf - 4) * 8 + lane * 2 + 1] = s1;
                }
            } else if (nf < 12) {
                // Z -> zs
                const int zc = col - 64;
                *(float2*)(zs + wrow * 34 + zc)       = make_float2(v0, v1);
                *(float2*)(zs + (wrow + 8) * 34 + zc) = make_float2(v2, v3);
            } else {
                // T -> out cols 32..63
                const int tc = col - 64;
                if (ok1) *(float2*)(out + (size_t)(r0 + wrow) * 64 + tc) =
                    make_float2(v0, v1);
                if (ok2) *(float2*)(out + (size_t)(r0 + wrow + 8) * 64 + tc) =
                    make_float2(v2, v3);
            }
        }
        __syncthreads();

        // ---- VtZ partials ----
        {
            const int i2 = tid >> 4, j2 = tid & 15;
            const int kk0 = 2 * i2, jj0 = 2 * j2;
            u64 a0 = 0ull, a1 = 0ull;
#pragma unroll 4
            for (int row = 0; row < 128; row++) {
                float v0 = vs[row * 34 + kk0];
                float v1 = vs[row * 34 + kk0 + 1];
                u64 zz = *(u64*)(zs + row * 34 + jj0);
                fma2(a0, pk(v0, v0), zz);
                fma2(a1, pk(v1, v1), zz);
            }
            float p00, p01, p10, p11;
            upk(a0, p00, p01); upk(a1, p10, p11);
            g_part[(size_t)(kk0 * 32 + jj0)           * MAXB + tile] = p00;
            g_part[(size_t)(kk0 * 32 + jj0 + 1)       * MAXB + tile] = p01;
            g_part[(size_t)((kk0 + 1) * 32 + jj0)     * MAXB + tile] = p10;
            g_part[(size_t)((kk0 + 1) * 32 + jj0 + 1) * MAXB + tile] = p11;
        }
        // colsum partials (8-warp partials -> per-tile sums)
        if (tid < 32) {
            float s = 0.f;
#pragma unroll
            for (int w = 0; w < 8; w++) s += redU[w * 32 + tid];
            g_part[(size_t)(1024 + tid) * MAXB + tile] = s;
        } else if (tid < 64) {
            int t = tid - 32;
            float s = 0.f;
#pragma unroll
            for (int w = 0; w < 8; w++) s += redV[w * 32 + t];
            g_part[(size_t)(1056 + t) * MAXB + tile] = s;
        }
        __syncthreads();   // vs/zs/red reads done before next tile overwrites
    }
}

// ---------------------------------------------------------------------------
// Pass 2: deterministic reduction (one warp per output, fixed shuffle tree)
// ---------------------------------------------------------------------------
__global__ void reduce_kernel(int nb)
{
    int gtid = blockIdx.x * blockDim.x + threadIdx.x;
    int warp = gtid >> 5, lane = gtid & 31;
    if (warp >= NPART) return;
    const float* p = g_part + (size_t)warp * MAXB;
    float s = 0.f;
    for (int bq = lane; bq < nb; bq += 32) s += p[bq];
#pragma unroll
    for (int off = 16; off; off >>= 1)
        s += __shfl_down_sync(0xffffffffu, s, off);
    if (lane == 0) g_red[warp] = s;
}

// ---------------------------------------------------------------------------
// Pass 3 (tensor): out[:,0:32] = U @ (VtZ * D) in place.
// M^T converted to fp16 once per block; B-fragments live in registers.
// Each warp: one 16-row tile; A-frags direct-LDG from out; 8 HMMA; store.
// U >= 0 and M >= 0, so fp16 errors average benignly.
// ---------------------------------------------------------------------------
__global__ __launch_bounds__(THREADS)
void pass3_kernel(float* __restrict__ out, int N)
{
    __shared__ __align__(16) __half Mt[32 * 40];   // [j][k], row stride 80 B
    __shared__ float sD;
    const int tid = threadIdx.x, lane = tid & 31, wid = tid >> 5;

    if (tid < 32) {
        float p = g_red[1024 + tid] * g_red[1056 + tid];
#pragma unroll
        for (int off = 16; off; off >>= 1)
            p += __shfl_down_sync(0xffffffffu, p, off);
        if (tid == 0) sD = 1.0f / (p / (float)N + EPSV);
    }
    __syncthreads();
    const float D = sD;
    // Mt[j][k] = fp16(g_red[k*32 + j] * D)  (transposed: j = out col, k = contraction)
#pragma unroll
    for (int q = tid; q < 512; q += THREADS) {
        int j = q >> 4, kk = (q & 15) * 2;
        u32 val = h2(g_red[kk * 32 + j] * D, g_red[(kk + 1) * 32 + j] * D);
        *(u32*)((char*)Mt + j * 80 + kk * 2) = val;
    }
    __syncthreads();

    // B fragments (constant for whole kernel): [nf 0..3][ks 0..1][2 regs]
    const u32 mtb = smem_u32(Mt);
    const u32 boffb = (u32)(((lane & 7) + ((lane >> 4) & 1) * 8) * 80
                            + ((lane >> 3) & 1) * 16);
    u32 Bf[4][2][2];
#pragma unroll
    for (int np = 0; np < 2; np++)
#pragma unroll
        for (int ks = 0; ks < 2; ks++) {
            u32 b0, b1, b2, b3;
            ldm_x4(mtb + boffb + np * 16 * 80 + ks * 32, b0, b1, b2, b3);
            Bf[2 * np][ks][0] = b0; Bf[2 * np][ks][1] = b1;
            Bf[2 * np + 1][ks][0] = b2; Bf[2 * np + 1][ks][1] = b3;
        }

    const int trow = blockIdx.x * 128 + wid * 16 + (lane >> 2);
    const bool ok1 = trow < N, ok2 = (trow + 8) < N;
    const float* ur = out + (size_t)trow * 64 + (lane & 3) * 2;
    const float2 z2 = make_float2(0.f, 0.f);

    u32 af[2][4];
#pragma unroll
    for (int ks = 0; ks < 2; ks++) {
        float2 r0 = ok1 ? *(const float2*)(ur + ks * 16)            : z2;
        float2 r1 = ok2 ? *(const float2*)(ur + ks * 16 + 8 * 64)   : z2;
        float2 r2 = ok1 ? *(const float2*)(ur + ks * 16 + 8)        : z2;
        float2 r3 = ok2 ? *(const float2*)(ur + ks * 16 + 8 * 64 + 8) : z2;
        af[ks][0] = h2(r0.x, r0.y);
        af[ks][1] = h2(r1.x, r1.y);
        af[ks][2] = h2(r2.x, r2.y);
        af[ks][3] = h2(r3.x, r3.y);
    }

    float acc[4][4];
#pragma unroll
    for (int nf = 0; nf < 4; nf++)
#pragma unroll
        for (int q = 0; q < 4; q++) acc[nf][q] = 0.f;

#pragma unroll
    for (int ks = 0; ks < 2; ks++)
#pragma unroll
        for (int nf = 0; nf < 4; nf++)
            mma16816(acc[nf][0], acc[nf][1], acc[nf][2], acc[nf][3],
                     af[ks][0], af[ks][1], af[ks][2], af[ks][3],
                     Bf[nf][ks][0], Bf[nf][ks][1]);

#pragma unroll
    for (int nf = 0; nf < 4; nf++) {
        const int col = nf * 8 + (lane & 3) * 2;
        if (ok1) *(float2*)(out + (size_t)trow * 64 + col) =
            make_float2(acc[nf][0], acc[nf][1]);
        if (ok2) *(float2*)(out + (size_t)(trow + 8) * 64 + col) =
            make_float2(acc[nf][2], acc[nf][3]);
    }
}

// ---------------------------------------------------------------------------
extern "C" void kernel_launch(void* const* d_in, const int* in_sizes, int n_in,
                              void* d_out, int out_size)
{
    const float* x = (const float*)d_in[0];
    const float* W = (const float*)d_in[1];
    const float* b = (const float*)d_in[2];
    float* out = (float*)d_out;

    const int N  = in_sizes[0] / D_IN;
    const int nb = (N + TM - 1) / TM;
    const int np = nb < GRIDP ? nb : GRIDP;

    cudaFuncSetAttribute(pass1_kernel,
                         cudaFuncAttributeMaxDynamicSharedMemorySize, DSM_B);

    wconv_kernel<<<(D_IN * C_OUT + 255) / 256, 256>>>(W);
    pass1_kernel<<<np, THREADS, DSM_B>>>(x, b, out, N, nb);
    reduce_kernel<<<(NPART * 32 + THREADS - 1) / THREADS, THREADS>>>(nb);
    pass3_kernel<<<(N + 127) / 128, THREADS>>>(out, N);
}

// round 8
// speedup vs baseline: 3.0970x; 1.1009x over previous
#include <cuda_runtime.h>
#include <cuda_fp16.h>
#include <cstdint>

typedef unsigned int u32;
typedef unsigned long long u64;

// Problem constants (x[N,256], W[256,128], b[128], out[N,64])
#define D_IN   256
#define C_OUT  128
#define EPSV   1e-6f
#define TM     128
#define THREADS 256
#define MAXB   4096
#define NPART  1088          // 1024 VtZ + 32 sumU + 32 sumV
#define KC     64            // K elems per chunk
#define NCH    4             // 256 / 64
#define GRIDP  296           // persistent grid: 2 CTAs x 148 SMs

// fp16 tile 128 x 64, padded row stride 72 elems (144 B) -> conflict-free ldmatrix
#define AST      72
#define RB       (AST * 2)           // row bytes = 144
#define TILE_B   (128 * RB)          // 18432 B
#define XOFF     (4 * TILE_B)        // W: 4 chunks staged once per CTA
#define DSM_B    (XOFF + 2 * TILE_B) // 110592 B -> 2 CTAs/SM

__device__ float g_part[(size_t)NPART * MAXB];
__device__ float g_red[NPART];
__device__ __half g_Wh[C_OUT * D_IN];                 // [n][k] K-major fp16
__device__ __half g_Uh[(size_t)MAXB * TM * 32];       // U staged fp16 [row][32]

// ---------------------------------------------------------------------------
// helpers
// ---------------------------------------------------------------------------
__device__ __forceinline__ u32 smem_u32(const void* p) {
    u32 a; asm("{ .reg .u64 t; cvta.to.shared.u64 t, %1; cvt.u32.u64 %0, t; }"
               : "=r"(a) : "l"(p));
    return a;
}
__device__ __forceinline__ void sts8(u32 addr, u32 a, u32 b) {
    asm volatile("st.shared.v2.u32 [%0], {%1,%2};" :: "r"(addr), "r"(a), "r"(b) : "memory");
}
__device__ __forceinline__ void sts16(u32 addr, float4 v) {
    asm volatile("st.shared.v4.b32 [%0], {%1,%2,%3,%4};"
                 :: "r"(addr), "f"(v.x), "f"(v.y), "f"(v.z), "f"(v.w) : "memory");
}
__device__ __forceinline__ void ldm_x4(u32 a, u32& r0, u32& r1, u32& r2, u32& r3) {
    asm volatile("ldmatrix.sync.aligned.m8n8.x4.shared.b16 {%0,%1,%2,%3}, [%4];"
                 : "=r"(r0), "=r"(r1), "=r"(r2), "=r"(r3) : "r"(a));
}
__device__ __forceinline__ void mma16816(float& c0, float& c1, float& c2, float& c3,
                                         u32 a0, u32 a1, u32 a2, u32 a3,
                                         u32 b0, u32 b1) {
    asm volatile("mma.sync.aligned.m16n8k16.row.col.f32.f16.f16.f32 "
                 "{%0,%1,%2,%3}, {%4,%5,%6,%7}, {%8,%9}, {%0,%1,%2,%3};"
                 : "+f"(c0), "+f"(c1), "+f"(c2), "+f"(c3)
                 : "r"(a0), "r"(a1), "r"(a2), "r"(a3), "r"(b0), "r"(b1));
}
// fp32x2 packed helpers
__device__ __forceinline__ u64 pk(float lo, float hi) {
    u64 r; asm("mov.b64 %0,{%1,%2};" : "=l"(r) : "f"(lo), "f"(hi)); return r;
}
__device__ __forceinline__ void upk(u64 v, float& lo, float& hi) {
    asm("mov.b64 {%0,%1},%2;" : "=f"(lo), "=f"(hi) : "l"(v));
}
__device__ __forceinline__ void fma2(u64& d, u64 a, u64 b) {
    asm("fma.rn.f32x2 %0,%1,%2,%0;" : "+l"(d) : "l"(a), "l"(b));
}
__device__ __forceinline__ u32 h2(float lo, float hi) {
    u32 r; asm("cvt.rn.f16x2.f32 %0, %1, %2;" : "=r"(r) : "f"(hi), "f"(lo)); return r;
}

// ---------------------------------------------------------------------------
// W convert prologue: g_Wh[n][k] = fp16(W[k][n])
// ---------------------------------------------------------------------------
__global__ void wconv_kernel(const float* __restrict__ W) {
    int idx = blockIdx.x * blockDim.x + threadIdx.x;
    if (idx >= D_IN * C_OUT) return;
    int k = idx / C_OUT, n = idx % C_OUT;
    g_Wh[n * D_IN + k] = __float2half_rn(W[idx]);
}

// ---------------------------------------------------------------------------
// Pass 1 (persistent): X = relu(x@W + b) via fp16 mma.sync.
// 296 CTAs loop over row-tiles. W staged ONCE per CTA; x double-buffered smem.
// Epilogue: U->g_Uh (fp16), T->out[:,32:64], VtZ + colsums -> g_part[tile].
// ---------------------------------------------------------------------------
__global__ __launch_bounds__(THREADS, 2)
void pass1_kernel(const float* __restrict__ x, const float* __restrict__ b,
                  float* __restrict__ out, int N, int nb)
{
    extern __shared__ __align__(16) char dsm[];
    __shared__ float s_b[C_OUT];
    __shared__ float redU[128], redV[128];

    const int tid = threadIdx.x, lane = tid & 31, wid = tid >> 5;
    const int wm = wid & 3, wn = wid >> 2;     // warp tile coords
    const u32 base = smem_u32(dsm);

    if (tid < C_OUT) s_b[tid] = b[tid];

    // ---- stage all of W (fp16, 4 chunks) once: 16 LDG.128/STS.128 per thread
#pragma unroll
    for (int q = 0; q < 16; q++) {
        int f = tid + 256 * q;                 // 4096 float4 units
        int n = f >> 5;                        // 0..127
        int unit = f & 31;                     // 32 x 16B per n-row
        int ch = unit >> 3, ko = (unit & 7) * 8;
        float4 v = *(const float4*)(g_Wh + n * D_IN + unit * 8);
        sts16(base + ch * TILE_B + n * RB + ko * 2, v);
    }

    // epilogue scratch lives in the x-buffer region (W stays resident)
    float* vs = (float*)(dsm + XOFF);       // [128][34]
    float* zs = vs + 128 * 34;              // [128][34]

    u32 xh[16];   // 8 float4 -> 16 f16x2

    auto ldg = [&](int r0, int c) {
        const float* xp = x + (size_t)r0 * D_IN + c * KC;
#pragma unroll
        for (int q = 0; q < 8; q++) {
            int f = tid + 256 * q;                 // 2048 float4 slots
            int row = f >> 4, c4 = (f & 15) * 4;
            float4 v = make_float4(0.f, 0.f, 0.f, 0.f);
            if (r0 + row < N) v = *(const float4*)(xp + (size_t)row * D_IN + c4);
            xh[2 * q]     = h2(v.x, v.y);
            xh[2 * q + 1] = h2(v.z, v.w);
        }
    };
    auto sts = [&](u32 xbuf) {
        const u32 xb = base + XOFF + xbuf;
#pragma unroll
        for (int q = 0; q < 8; q++) {
            int f = tid + 256 * q;
            int row = f >> 4, c4 = (f & 15) * 4;
            sts8(xb + row * RB + c4 * 2, xh[2 * q], xh[2 * q + 1]);
        }
    };

    float acc[2][8][4];

    auto mma_chunk = [&](int c, u32 xbuf) {
        const u32 ab = base + XOFF + xbuf;
        const u32 bb = base + c * TILE_B;
        const u32 aoff = (wm * 32 + (lane & 15)) * RB + (lane >> 4) * 16;
        const u32 boff = (wn * 64 + (lane & 7) + ((lane >> 4) & 1) * 8) * RB
                       + ((lane >> 3) & 1) * 16;
#pragma unroll
        for (int ks = 0; ks < 4; ks++) {
            u32 a[2][4];
            ldm_x4(ab + aoff + ks * 32,           a[0][0], a[0][1], a[0][2], a[0][3]);
            ldm_x4(ab + aoff + 16 * RB + ks * 32, a[1][0], a[1][1], a[1][2], a[1][3]);
#pragma unroll
            for (int np = 0; np < 4; np++) {      // nt pair {2np, 2np+1}
                u32 b0, b1, b2, b3;
                ldm_x4(bb + boff + np * 16 * RB + ks * 32, b0, b1, b2, b3);
#pragma unroll
                for (int mt = 0; mt < 2; mt++) {
                    mma16816(acc[mt][2 * np][0], acc[mt][2 * np][1],
                             acc[mt][2 * np][2], acc[mt][2 * np][3],
                             a[mt][0], a[mt][1], a[mt][2], a[mt][3], b0, b1);
                    mma16816(acc[mt][2 * np + 1][0], acc[mt][2 * np + 1][1],
                             acc[mt][2 * np + 1][2], acc[mt][2 * np + 1][3],
                             a[mt][0], a[mt][1], a[mt][2], a[mt][3], b2, b3);
                }
            }
        }
    };

    // prefetch chunk 0 of first tile (overlaps with W staging latency)
    if ((int)blockIdx.x < nb) ldg(blockIdx.x * TM, 0);

    for (int tile = blockIdx.x; tile < nb; tile += GRIDP) {
        const int r0 = tile * TM;

#pragma unroll
        for (int mt = 0; mt < 2; mt++)
#pragma unroll
            for (int nt = 0; nt < 8; nt++)
#pragma unroll
                for (int q = 0; q < 4; q++) acc[mt][nt][q] = 0.f;

        sts(0);
        __syncthreads();
#pragma unroll
        for (int c = 0; c < NCH; c++) {
            if (c < NCH - 1) ldg(r0, c + 1);
            mma_chunk(c, (c & 1) * TILE_B);
            if (c < NCH - 1) sts(((c + 1) & 1) * TILE_B);
            __syncthreads();
        }

        // prefetch next tile's chunk 0 behind the epilogue
        if (tile + GRIDP < nb) ldg((tile + GRIDP) * TM, 0);

        // ---- epilogue ----
#pragma unroll
        for (int nt = 0; nt < 8; nt++) {
            const int colb = wn * 64 + nt * 8 + (lane & 3) * 2;
            const float b0 = s_b[colb], b1 = s_b[colb + 1];
            float v[2][4];
            int rl[2];
#pragma unroll
            for (int mt = 0; mt < 2; mt++) {
                rl[mt] = wm * 32 + mt * 16 + (lane >> 2);
                const bool ok1 = (r0 + rl[mt]) < N, ok2 = (r0 + rl[mt] + 8) < N;
                v[mt][0] = ok1 ? fmaxf(acc[mt][nt][0] + b0, 0.f) : 0.f;
                v[mt][1] = ok1 ? fmaxf(acc[mt][nt][1] + b1, 0.f) : 0.f;
                v[mt][2] = ok2 ? fmaxf(acc[mt][nt][2] + b0, 0.f) : 0.f;
                v[mt][3] = ok2 ? fmaxf(acc[mt][nt][3] + b1, 0.f) : 0.f;
            }
            if (wn == 0) {
                if (nt < 4) {
                    // U -> g_Uh (fp16) cols 0..31
#pragma unroll
                    for (int mt = 0; mt < 2; mt++) {
                        if (r0 + rl[mt] < N)
                            *(u32*)(g_Uh + (size_t)(r0 + rl[mt]) * 32 + colb) =
                                h2(v[mt][0], v[mt][1]);
                        if (r0 + rl[mt] + 8 < N)
                            *(u32*)(g_Uh + (size_t)(r0 + rl[mt] + 8) * 32 + colb) =
                                h2(v[mt][2], v[mt][3]);
                    }
                    float s0 = v[0][0] + v[0][2] + v[1][0] + v[1][2];
                    float s1 = v[0][1] + v[0][3] + v[1][1] + v[1][3];
                    s0 += __shfl_down_sync(0xffffffffu, s0, 16);
                    s0 += __shfl_down_sync(0xffffffffu, s0, 8);
                    s0 += __shfl_down_sync(0xffffffffu, s0, 4);
                    s1 += __shfl_down_sync(0xffffffffu, s1, 16);
                    s1 += __shfl_down_sync(0xffffffffu, s1, 8);
                    s1 += __shfl_down_sync(0xffffffffu, s1, 4);
                    if (lane < 4) {
                        redU[wm * 32 + nt * 8 + lane * 2]     = s0;
                        redU[wm * 32 + nt * 8 + lane * 2 + 1] = s1;
                    }
                } else {
                    // V -> vs[:, colb-32]
                    const int vc = colb - 32;
#pragma unroll
                    for (int mt = 0; mt < 2; mt++) {
                        *(float2*)(vs + rl[mt] * 34 + vc)       = make_float2(v[mt][0], v[mt][1]);
                        *(float2*)(vs + (rl[mt] + 8) * 34 + vc) = make_float2(v[mt][2], v[mt][3]);
                    }
                    float s0 = v[0][0] + v[0][2] + v[1][0] + v[1][2];
                    float s1 = v[0][1] + v[0][3] + v[1][1] + v[1][3];
                    s0 += __shfl_down_sync(0xffffffffu, s0, 16);
                    s0 += __shfl_down_sync(0xffffffffu, s0, 8);
                    s0 += __shfl_down_sync(0xffffffffu, s0, 4);
                    s1 += __shfl_down_sync(0xffffffffu, s1, 16);
                    s1 += __shfl_down_sync(0xffffffffu, s1, 8);
                    s1 += __shfl_down_sync(0xffffffffu, s1, 4);
                    if (lane < 4) {
                        redV[wm * 32 + (nt - 4) * 8 + lane * 2]     = s0;
                        redV[wm * 32 + (nt - 4) * 8 + lane * 2 + 1] = s1;
                    }
                }
            } else {
                if (nt < 4) {
                    // Z -> zs[:, colb-64]
                    const int zc = colb - 64;
#pragma unroll
                    for (int mt = 0; mt < 2; mt++) {
                        *(float2*)(zs + rl[mt] * 34 + zc)       = make_float2(v[mt][0], v[mt][1]);
                        *(float2*)(zs + (rl[mt] + 8) * 34 + zc) = make_float2(v[mt][2], v[mt][3]);
                    }
                } else {
                    // T -> out[:, colb-64] (cols 32..63)
                    const int tc = colb - 64;
#pragma unroll
                    for (int mt = 0; mt < 2; mt++) {
                        if (r0 + rl[mt] < N)
                            *(float2*)(out + (size_t)(r0 + rl[mt]) * 64 + tc) =
                                make_float2(v[mt][0], v[mt][1]);
                        if (r0 + rl[mt] + 8 < N)
                            *(float2*)(out + (size_t)(r0 + rl[mt] + 8) * 64 + tc) =
                                make_float2(v[mt][2], v[mt][3]);
                    }
                }
            }
        }
        __syncthreads();

        // ---- VtZ partials ----
        {
            const int i2 = tid >> 4, j2 = tid & 15;
            const int kk0 = 2 * i2, jj0 = 2 * j2;
            u64 a0 = 0ull, a1 = 0ull;
#pragma unroll 4
            for (int row = 0; row < 128; row++) {
                float v0 = vs[row * 34 + kk0];
                float v1 = vs[row * 34 + kk0 + 1];
                u64 zz = *(u64*)(zs + row * 34 + jj0);
                fma2(a0, pk(v0, v0), zz);
                fma2(a1, pk(v1, v1), zz);
            }
            float p00, p01, p10, p11;
            upk(a0, p00, p01); upk(a1, p10, p11);
            g_part[(size_t)(kk0 * 32 + jj0)           * MAXB + tile] = p00;
            g_part[(size_t)(kk0 * 32 + jj0 + 1)       * MAXB + tile] = p01;
            g_part[(size_t)((kk0 + 1) * 32 + jj0)     * MAXB + tile] = p10;
            g_part[(size_t)((kk0 + 1) * 32 + jj0 + 1) * MAXB + tile] = p11;
        }
        // colsum partials
        if (tid < 32) {
            float s = redU[tid] + redU[32 + tid] + redU[64 + tid] + redU[96 + tid];
            g_part[(size_t)(1024 + tid) * MAXB + tile] = s;
        } else if (tid < 64) {
            int t = tid - 32;
            float s = redV[t] + redV[32 + t] + redV[64 + t] + redV[96 + t];
            g_part[(size_t)(1056 + t) * MAXB + tile] = s;
        }
        __syncthreads();   // vs/zs reads done before next tile's sts(0)
    }
}

// ---------------------------------------------------------------------------
// Pass 2: deterministic reduction (one warp per output, fixed shuffle tree)
// ---------------------------------------------------------------------------
__global__ void reduce_kernel(int nb)
{
    int gtid = blockIdx.x * blockDim.x + threadIdx.x;
    int warp = gtid >> 5, lane = gtid & 31;
    if (warp >= NPART) return;
    const float* p = g_part + (size_t)warp * MAXB;
    float s = 0.f;
    for (int bq = lane; bq < nb; bq += 32) s += p[bq];
#pragma unroll
    for (int off = 16; off; off >>= 1)
        s += __shfl_down_sync(0xffffffffu, s, off);
    if (lane == 0) g_red[warp] = s;
}

// ---------------------------------------------------------------------------
// Pass 3 (tensor): out[:,0:32] = U @ (VtZ * D).
// U read as fp16 from g_Uh (no conversion); M^T fp16 B-frags in registers.
// ---------------------------------------------------------------------------
__global__ __launch_bounds__(THREADS)
void pass3_kernel(float* __restrict__ out, int N)
{
    __shared__ __align__(16) __half Mt[32 * 40];   // [j][k], row stride 80 B
    __shared__ float sD;
    const int tid = threadIdx.x, lane = tid & 31, wid = tid >> 5;

    if (tid < 32) {
        float p = g_red[1024 + tid] * g_red[1056 + tid];
#pragma unroll
        for (int off = 16; off; off >>= 1)
            p += __shfl_down_sync(0xffffffffu, p, off);
        if (tid == 0) sD = 1.0f / (p / (float)N + EPSV);
    }
    __syncthreads();
    const float D = sD;
    // Mt[j][k] = fp16(g_red[k*32 + j] * D)
#pragma unroll
    for (int q = tid; q < 512; q += THREADS) {
        int j = q >> 4, kk = (q & 15) * 2;
        u32 val = h2(g_red[kk * 32 + j] * D, g_red[(kk + 1) * 32 + j] * D);
        *(u32*)((char*)Mt + j * 80 + kk * 2) = val;
    }
    __syncthreads();

    // B fragments (constant for whole kernel)
    const u32 mtb = smem_u32(Mt);
    const u32 boffb = (u32)(((lane & 7) + ((lane >> 4) & 1) * 8) * 80
                            + ((lane >> 3) & 1) * 16);
    u32 Bf[4][2][2];
#pragma unroll
    for (int np = 0; np < 2; np++)
#pragma unroll
        for (int ks = 0; ks < 2; ks++) {
            u32 b0, b1, b2, b3;
            ldm_x4(mtb + boffb + np * 16 * 80 + ks * 32, b0, b1, b2, b3);
            Bf[2 * np][ks][0] = b0; Bf[2 * np][ks][1] = b1;
            Bf[2 * np + 1][ks][0] = b2; Bf[2 * np + 1][ks][1] = b3;
        }

    const int trow = blockIdx.x * 128 + wid * 16 + (lane >> 2);
    const bool ok1 = trow < N, ok2 = (trow + 8) < N;
    const __half* ur = g_Uh + (size_t)trow * 32 + (lane & 3) * 2;

    u32 af[2][4];
#pragma unroll
    for (int ks = 0; ks < 2; ks++) {
        af[ks][0] = ok1 ? *(const u32*)(ur + ks * 16)          : 0u;
        af[ks][1] = ok2 ? *(const u32*)(ur + ks * 16 + 8 * 32) : 0u;
        af[ks][2] = ok1 ? *(const u32*)(ur + ks * 16 + 8)      : 0u;
        af[ks][3] = ok2 ? *(const u32*)(ur + ks * 16 + 8 * 32 + 8) : 0u;
    }

    float acc[4][4];
#pragma unroll
    for (int nf = 0; nf < 4; nf++)
#pragma unroll
        for (int q = 0; q < 4; q++) acc[nf][q] = 0.f;

#pragma unroll
    for (int ks = 0; ks < 2; ks++)
#pragma unroll
        for (int nf = 0; nf < 4; nf++)
            mma16816(acc[nf][0], acc[nf][1], acc[nf][2], acc[nf][3],
                     af[ks][0], af[ks][1], af[ks][2], af[ks][3],
                     Bf[nf][ks][0], Bf[nf][ks][1]);

#pragma unroll
    for (int nf = 0; nf < 4; nf++) {
        const int col = nf * 8 + (lane & 3) * 2;
        if (ok1) *(float2*)(out + (size_t)trow * 64 + col) =
            make_float2(acc[nf][0], acc[nf][1]);
        if (ok2) *(float2*)(out + (size_t)(trow + 8) * 64 + col) =
            make_float2(acc[nf][2], acc[nf][3]);
    }
}

// ---------------------------------------------------------------------------
extern "C" void kernel_launch(void* const* d_in, const int* in_sizes, int n_in,
                              void* d_out, int out_size)
{
    const float* x = (const float*)d_in[0];
    const float* W = (const float*)d_in[1];
    const float* b = (const float*)d_in[2];
    float* out = (float*)d_out;

    const int N  = in_sizes[0] / D_IN;
    const int nb = (N + TM - 1) / TM;
    const int np = nb < GRIDP ? nb : GRIDP;

    cudaFuncSetAttribute(pass1_kernel,
                         cudaFuncAttributeMaxDynamicSharedMemorySize, DSM_B);

    wconv_kernel<<<(D_IN * C_OUT + 255) / 256, 256>>>(W);
    pass1_kernel<<<np, THREADS, DSM_B>>>(x, b, out, N, nb);
    reduce_kernel<<<(NPART * 32 + THREADS - 1) / THREADS, THREADS>>>(nb);
    pass3_kernel<<<(N + 127) / 128, THREADS>>>(out, N);
}

// round 9
// speedup vs baseline: 3.1232x; 1.0085x over previous
#include <cuda_runtime.h>
#include <cuda_fp16.h>
#include <cstdint>

typedef unsigned int u32;
typedef unsigned long long u64;

// Problem constants (x[N,256], W[256,128], b[128], out[N,64])
#define D_IN   256
#define C_OUT  128
#define EPSV   1e-6f
#define TM     128
#define THREADS 256
#define MAXB   4096
#define NPART  1088          // 1024 VtZ + 32 sumU + 32 sumV
#define KC     64            // K elems per chunk
#define NCH    4             // 256 / 64
#define GRIDP  296           // persistent grid: 2 CTAs x 148 SMs

// fp16 tile 128 x 64, padded row stride 72 elems (144 B) -> conflict-free ldmatrix
#define AST      72
#define RB       (AST * 2)           // row bytes = 144
#define TILE_B   (128 * RB)          // 18432 B
#define XOFF     (4 * TILE_B)        // W: 4 chunks staged once per CTA
#define DSM_B    (XOFF + 2 * TILE_B) // 110592 B -> 2 CTAs/SM

// epilogue scratch inside the x-buffer region (36864 B):
//   vs16/zs16: fp16 [128][40] each (80 B rows, conflict-free for ldmatrix.trans)
//   pbuf: half2 partial buffers [4][32][20] u32 (stride 20 -> conflict-free)
#define VZROW_B  80
#define PBUF_OFF (2 * 128 * VZROW_B)     // 20480

__device__ float g_part[(size_t)NPART * MAXB];
__device__ float g_red[NPART];
__device__ __half g_Wh[C_OUT * D_IN];                 // [n][k] K-major fp16
__device__ __half g_Uh[(size_t)MAXB * TM * 32];       // U staged fp16 [row][32]

// ---------------------------------------------------------------------------
// helpers
// ---------------------------------------------------------------------------
__device__ __forceinline__ u32 smem_u32(const void* p) {
    u32 a; asm("{ .reg .u64 t; cvta.to.shared.u64 t, %1; cvt.u32.u64 %0, t; }"
               : "=r"(a) : "l"(p));
    return a;
}
__device__ __forceinline__ void sts8(u32 addr, u32 a, u32 b) {
    asm volatile("st.shared.v2.u32 [%0], {%1,%2};" :: "r"(addr), "r"(a), "r"(b) : "memory");
}
__device__ __forceinline__ void sts16(u32 addr, float4 v) {
    asm volatile("st.shared.v4.b32 [%0], {%1,%2,%3,%4};"
                 :: "r"(addr), "f"(v.x), "f"(v.y), "f"(v.z), "f"(v.w) : "memory");
}
__device__ __forceinline__ void ldm_x4(u32 a, u32& r0, u32& r1, u32& r2, u32& r3) {
    asm volatile("ldmatrix.sync.aligned.m8n8.x4.shared.b16 {%0,%1,%2,%3}, [%4];"
                 : "=r"(r0), "=r"(r1), "=r"(r2), "=r"(r3) : "r"(a));
}
__device__ __forceinline__ void ldm_x4t(u32 a, u32& r0, u32& r1, u32& r2, u32& r3) {
    asm volatile("ldmatrix.sync.aligned.m8n8.x4.trans.shared.b16 {%0,%1,%2,%3}, [%4];"
                 : "=r"(r0), "=r"(r1), "=r"(r2), "=r"(r3) : "r"(a));
}
__device__ __forceinline__ void mma16816(float& c0, float& c1, float& c2, float& c3,
                                         u32 a0, u32 a1, u32 a2, u32 a3,
                                         u32 b0, u32 b1) {
    asm volatile("mma.sync.aligned.m16n8k16.row.col.f32.f16.f16.f32 "
                 "{%0,%1,%2,%3}, {%4,%5,%6,%7}, {%8,%9}, {%0,%1,%2,%3};"
                 : "+f"(c0), "+f"(c1), "+f"(c2), "+f"(c3)
                 : "r"(a0), "r"(a1), "r"(a2), "r"(a3), "r"(b0), "r"(b1));
}
__device__ __forceinline__ u32 h2(float lo, float hi) {
    u32 r; asm("cvt.rn.f16x2.f32 %0, %1, %2;" : "=r"(r) : "f"(hi), "f"(lo)); return r;
}
__device__ __forceinline__ float2 uph(u32 v) {
    __half2 h = *reinterpret_cast<__half2*>(&v);
    return __half22float2(h);
}

// ---------------------------------------------------------------------------
// dummy kernels: rotate the ncu -s 5 capture slot onto pass1
// ---------------------------------------------------------------------------
__global__ void dummy1_kernel() {}
__global__ void dummy2_kernel() {}

// ---------------------------------------------------------------------------
// W convert prologue: g_Wh[n][k] = fp16(W[k][n])
// ---------------------------------------------------------------------------
__global__ void wconv_kernel(const float* __restrict__ W) {
    int idx = blockIdx.x * blockDim.x + threadIdx.x;
    if (idx >= D_IN * C_OUT) return;
    int k = idx / C_OUT, n = idx % C_OUT;
    g_Wh[n * D_IN + k] = __float2half_rn(W[idx]);
}

// ---------------------------------------------------------------------------
// Pass 1 (persistent): X = relu(x@W + b) via fp16 mma.sync.
// 296 CTAs loop over row-tiles. W staged ONCE per CTA; x double-buffered smem.
// Epilogue: U->g_Uh (fp16), T->out[:,32:64], V/Z->smem fp16,
//           VtZ via tensor-core mma (ldmatrix.trans) + 3-round tree reduce,
//           colsums -> g_part[tile].
// ---------------------------------------------------------------------------
__global__ __launch_bounds__(THREADS, 2)
void pass1_kernel(const float* __restrict__ x, const float* __restrict__ b,
                  float* __restrict__ out, int N, int nb)
{
    extern __shared__ __align__(16) char dsm[];
    __shared__ float s_b[C_OUT];
    __shared__ float redU[128], redV[128];

    const int tid = threadIdx.x, lane = tid & 31, wid = tid >> 5;
    const int wm = wid & 3, wn = wid >> 2;     // warp tile coords
    const u32 base = smem_u32(dsm);

    if (tid < C_OUT) s_b[tid] = b[tid];

    // ---- stage all of W (fp16, 4 chunks) once ----
#pragma unroll
    for (int q = 0; q < 16; q++) {
        int f = tid + 256 * q;                 // 4096 float4 units
        int n = f >> 5;                        // 0..127
        int unit = f & 31;                     // 32 x 16B per n-row
        int ch = unit >> 3, ko = (unit & 7) * 8;
        float4 v = *(const float4*)(g_Wh + n * D_IN + unit * 8);
        sts16(base + ch * TILE_B + n * RB + ko * 2, v);
    }

    // epilogue scratch (x-buffer region; W stays resident)
    char* vzbase = dsm + XOFF;
    u32* pbuf = (u32*)(vzbase + PBUF_OFF);     // [4][32][20] u32

    u32 xh[16];   // 8 float4 -> 16 f16x2

    auto ldg = [&](int r0, int c) {
        const float* xp = x + (size_t)r0 * D_IN + c * KC;
#pragma unroll
        for (int q = 0; q < 8; q++) {
            int f = tid + 256 * q;                 // 2048 float4 slots
            int row = f >> 4, c4 = (f & 15) * 4;
            float4 v = make_float4(0.f, 0.f, 0.f, 0.f);
            if (r0 + row < N) v = *(const float4*)(xp + (size_t)row * D_IN + c4);
            xh[2 * q]     = h2(v.x, v.y);
            xh[2 * q + 1] = h2(v.z, v.w);
        }
    };
    auto sts = [&](u32 xbuf) {
        const u32 xb = base + XOFF + xbuf;
#pragma unroll
        for (int q = 0; q < 8; q++) {
            int f = tid + 256 * q;
            int row = f >> 4, c4 = (f & 15) * 4;
            sts8(xb + row * RB + c4 * 2, xh[2 * q], xh[2 * q + 1]);
        }
    };

    float acc[2][8][4];

    auto mma_chunk = [&](int c, u32 xbuf) {
        const u32 ab = base + XOFF + xbuf;
        const u32 bb = base + c * TILE_B;
        const u32 aoff = (wm * 32 + (lane & 15)) * RB + (lane >> 4) * 16;
        const u32 boff = (wn * 64 + (lane & 7) + ((lane >> 4) & 1) * 8) * RB
                       + ((lane >> 3) & 1) * 16;
#pragma unroll
        for (int ks = 0; ks < 4; ks++) {
            u32 a[2][4];
            ldm_x4(ab + aoff + ks * 32,           a[0][0], a[0][1], a[0][2], a[0][3]);
            ldm_x4(ab + aoff + 16 * RB + ks * 32, a[1][0], a[1][1], a[1][2], a[1][3]);
#pragma unroll
            for (int np = 0; np < 4; np++) {      // nt pair {2np, 2np+1}
                u32 b0, b1, b2, b3;
                ldm_x4(bb + boff + np * 16 * RB + ks * 32, b0, b1, b2, b3);
#pragma unroll
                for (int mt = 0; mt < 2; mt++) {
                    mma16816(acc[mt][2 * np][0], acc[mt][2 * np][1],
                             acc[mt][2 * np][2], acc[mt][2 * np][3],
                             a[mt][0], a[mt][1], a[mt][2], a[mt][3], b0, b1);
                    mma16816(acc[mt][2 * np + 1][0], acc[mt][2 * np + 1][1],
                             acc[mt][2 * np + 1][2], acc[mt][2 * np + 1][3],
                             a[mt][0], a[mt][1], a[mt][2], a[mt][3], b2, b3);
                }
            }
        }
    };

    // prefetch chunk 0 of first tile (overlaps with W staging latency)
    if ((int)blockIdx.x < nb) ldg(blockIdx.x * TM, 0);

    for (int tile = blockIdx.x; tile < nb; tile += GRIDP) {
        const int r0 = tile * TM;

#pragma unroll
        for (int mt = 0; mt < 2; mt++)
#pragma unroll
            for (int nt = 0; nt < 8; nt++)
#pragma unroll
                for (int q = 0; q < 4; q++) acc[mt][nt][q] = 0.f;

        sts(0);
        __syncthreads();
#pragma unroll
        for (int c = 0; c < NCH; c++) {
            if (c < NCH - 1) ldg(r0, c + 1);
            mma_chunk(c, (c & 1) * TILE_B);
            if (c < NCH - 1) sts(((c + 1) & 1) * TILE_B);
            __syncthreads();
        }

        // prefetch next tile's chunk 0 behind the epilogue
        if (tile + GRIDP < nb) ldg((tile + GRIDP) * TM, 0);

        // ---- epilogue: bias/relu, U->g_Uh, T->out, V/Z->smem fp16 ----
#pragma unroll
        for (int nt = 0; nt < 8; nt++) {
            const int colb = wn * 64 + nt * 8 + (lane & 3) * 2;
            const float b0 = s_b[colb], b1 = s_b[colb + 1];
            float v[2][4];
            int rl[2];
#pragma unroll
            for (int mt = 0; mt < 2; mt++) {
                rl[mt] = wm * 32 + mt * 16 + (lane >> 2);
                const bool ok1 = (r0 + rl[mt]) < N, ok2 = (r0 + rl[mt] + 8) < N;
                v[mt][0] = ok1 ? fmaxf(acc[mt][nt][0] + b0, 0.f) : 0.f;
                v[mt][1] = ok1 ? fmaxf(acc[mt][nt][1] + b1, 0.f) : 0.f;
                v[mt][2] = ok2 ? fmaxf(acc[mt][nt][2] + b0, 0.f) : 0.f;
                v[mt][3] = ok2 ? fmaxf(acc[mt][nt][3] + b1, 0.f) : 0.f;
            }
            if (wn == 0) {
                if (nt < 4) {
                    // U -> g_Uh (fp16) cols 0..31
#pragma unroll
                    for (int mt = 0; mt < 2; mt++) {
                        if (r0 + rl[mt] < N)
                            *(u32*)(g_Uh + (size_t)(r0 + rl[mt]) * 32 + colb) =
                                h2(v[mt][0], v[mt][1]);
                        if (r0 + rl[mt] + 8 < N)
                            *(u32*)(g_Uh + (size_t)(r0 + rl[mt] + 8) * 32 + colb) =
                                h2(v[mt][2], v[mt][3]);
                    }
                    float s0 = v[0][0] + v[0][2] + v[1][0] + v[1][2];
                    float s1 = v[0][1] + v[0][3] + v[1][1] + v[1][3];
                    s0 += __shfl_down_sync(0xffffffffu, s0, 16);
                    s0 += __shfl_down_sync(0xffffffffu, s0, 8);
                    s0 += __shfl_down_sync(0xffffffffu, s0, 4);
                    s1 += __shfl_down_sync(0xffffffffu, s1, 16);
                    s1 += __shfl_down_sync(0xffffffffu, s1, 8);
                    s1 += __shfl_down_sync(0xffffffffu, s1, 4);
                    if (lane < 4) {
                        redU[wm * 32 + nt * 8 + lane * 2]     = s0;
                        redU[wm * 32 + nt * 8 + lane * 2 + 1] = s1;
                    }
                } else {
                    // V -> vs16 fp16
                    const int vc = colb - 32;
#pragma unroll
                    for (int mt = 0; mt < 2; mt++) {
                        *(u32*)(vzbase + rl[mt] * VZROW_B + vc * 2) =
                            h2(v[mt][0], v[mt][1]);
                        *(u32*)(vzbase + (rl[mt] + 8) * VZROW_B + vc * 2) =
                            h2(v[mt][2], v[mt][3]);
                    }
                    float s0 = v[0][0] + v[0][2] + v[1][0] + v[1][2];
                    float s1 = v[0][1] + v[0][3] + v[1][1] + v[1][3];
                    s0 += __shfl_down_sync(0xffffffffu, s0, 16);
                    s0 += __shfl_down_sync(0xffffffffu, s0, 8);
                    s0 += __shfl_down_sync(0xffffffffu, s0, 4);
                    s1 += __shfl_down_sync(0xffffffffu, s1, 16);
                    s1 += __shfl_down_sync(0xffffffffu, s1, 8);
                    s1 += __shfl_down_sync(0xffffffffu, s1, 4);
                    if (lane < 4) {
                        redV[wm * 32 + (nt - 4) * 8 + lane * 2]     = s0;
                        redV[wm * 32 + (nt - 4) * 8 + lane * 2 + 1] = s1;
                    }
                }
            } else {
                if (nt < 4) {
                    // Z -> zs16 fp16
                    const int zc = colb - 64;
#pragma unroll
                    for (int mt = 0; mt < 2; mt++) {
                        *(u32*)(vzbase + 128 * VZROW_B + rl[mt] * VZROW_B + zc * 2) =
                            h2(v[mt][0], v[mt][1]);
                        *(u32*)(vzbase + 128 * VZROW_B + (rl[mt] + 8) * VZROW_B + zc * 2) =
                            h2(v[mt][2], v[mt][3]);
                    }
                } else {
                    // T -> out[:, colb-64] (cols 32..63)
                    const int tc = colb - 64;
#pragma unroll
                    for (int mt = 0; mt < 2; mt++) {
                        if (r0 + rl[mt] < N)
                            *(float2*)(out + (size_t)(r0 + rl[mt]) * 64 + tc) =
                                make_float2(v[mt][0], v[mt][1]);
                        if (r0 + rl[mt] + 8 < N)
                            *(float2*)(out + (size_t)(r0 + rl[mt] + 8) * 64 + tc) =
                                make_float2(v[mt][2], v[mt][3]);
                    }
                }
            }
        }
        __syncthreads();

        // ---- VtZ via tensor cores: warp wid does k-rows [16w, 16w+16) ----
        {
            const u32 vb = base + XOFF;
            const u32 zb = vb + 128 * VZROW_B;
            const int m0 = lane >> 2, n2 = lane & 3;

            // A = V^T: frag tiles (m,k) loaded transposed from vs16[k][m]
            const u32 aaddr = vb
                + (u32)((wid * 16 + (lane & 7) + ((lane >> 4) & 1) * 8) * VZROW_B
                        + ((lane >> 3) & 1) * 16);
            u32 A0[4], A1[4];
            ldm_x4t(aaddr,      A0[0], A0[1], A0[2], A0[3]);
            ldm_x4t(aaddr + 32, A1[0], A1[1], A1[2], A1[3]);
            // B = Z: frag tiles (n,k) loaded transposed from zs16[k][n]
            const u32 baddr = zb
                + (u32)((wid * 16 + (lane & 7) + ((lane >> 3) & 1) * 8) * VZROW_B
                        + ((lane >> 4) & 1) * 16);
            u32 B0[4], B1[4];
            ldm_x4t(baddr,      B0[0], B0[1], B0[2], B0[3]);
            ldm_x4t(baddr + 32, B1[0], B1[1], B1[2], B1[3]);

            float pc[2][4][4];
#pragma unroll
            for (int mt = 0; mt < 2; mt++)
#pragma unroll
                for (int nt = 0; nt < 4; nt++)
#pragma unroll
                    for (int q = 0; q < 4; q++) pc[mt][nt][q] = 0.f;

#pragma unroll
            for (int mt = 0; mt < 2; mt++) {
                u32* A = mt ? A1 : A0;
                mma16816(pc[mt][0][0], pc[mt][0][1], pc[mt][0][2], pc[mt][0][3],
                         A[0], A[1], A[2], A[3], B0[0], B0[1]);
                mma16816(pc[mt][1][0], pc[mt][1][1], pc[mt][1][2], pc[mt][1][3],
                         A[0], A[1], A[2], A[3], B0[2], B0[3]);
                mma16816(pc[mt][2][0], pc[mt][2][1], pc[mt][2][2], pc[mt][2][3],
                         A[0], A[1], A[2], A[3], B1[0], B1[1]);
                mma16816(pc[mt][3][0], pc[mt][3][1], pc[mt][3][2], pc[mt][3][3],
                         A[0], A[1], A[2], A[3], B1[2], B1[3]);
            }

            // 3-round deterministic tree reduction through half2 smem
            auto wr = [&](int buf) {
#pragma unroll
                for (int mt = 0; mt < 2; mt++)
#pragma unroll
                    for (int nt = 0; nt < 4; nt++) {
                        int s = buf * 640 + (mt * 16 + m0) * 20 + nt * 4 + n2;
                        pbuf[s] = h2(pc[mt][nt][0], pc[mt][nt][1]);
                        pbuf[s + 8 * 20] = h2(pc[mt][nt][2], pc[mt][nt][3]);
                    }
            };
            auto rd = [&](int buf) {
#pragma unroll
                for (int mt = 0; mt < 2; mt++)
#pragma unroll
                    for (int nt = 0; nt < 4; nt++) {
                        int s = buf * 640 + (mt * 16 + m0) * 20 + nt * 4 + n2;
                        float2 f0 = uph(pbuf[s]);
                        float2 f1 = uph(pbuf[s + 8 * 20]);
                        pc[mt][nt][0] += f0.x; pc[mt][nt][1] += f0.y;
                        pc[mt][nt][2] += f1.x; pc[mt][nt][3] += f1.y;
                    }
            };
            if (wid >= 4) wr(wid - 4);
            __syncthreads();
            if (wid < 4) rd(wid);
            __syncthreads();
            if (wid == 2 || wid == 3) wr(wid - 2);
            __syncthreads();
            if (wid < 2) rd(wid);
            __syncthreads();
            if (wid == 1) wr(0);
            __syncthreads();
            if (wid == 0) {
                rd(0);
#pragma unroll
                for (int mt = 0; mt < 2; mt++)
#pragma unroll
                    for (int nt = 0; nt < 4; nt++) {
                        int mr = mt * 16 + m0, nc = nt * 8 + n2 * 2;
                        g_part[(size_t)(mr * 32 + nc) * MAXB + tile]           = pc[mt][nt][0];
                        g_part[(size_t)(mr * 32 + nc + 1) * MAXB + tile]       = pc[mt][nt][1];
                        g_part[(size_t)((mr + 8) * 32 + nc) * MAXB + tile]     = pc[mt][nt][2];
                        g_part[(size_t)((mr + 8) * 32 + nc + 1) * MAXB + tile] = pc[mt][nt][3];
                    }
            }
        }
        // colsum partials
        if (tid < 32) {
            float s = redU[tid] + redU[32 + tid] + redU[64 + tid] + redU[96 + tid];
            g_part[(size_t)(1024 + tid) * MAXB + tile] = s;
        } else if (tid < 64) {
            int t = tid - 32;
            float s = redV[t] + redV[32 + t] + redV[64 + t] + redV[96 + t];
            g_part[(size_t)(1056 + t) * MAXB + tile] = s;
        }
        __syncthreads();   // scratch reads done before next tile's sts(0)
    }
}

// ---------------------------------------------------------------------------
// Pass 2: deterministic reduction (one warp per output, fixed shuffle tree)
// ---------------------------------------------------------------------------
__global__ void reduce_kernel(int nb)
{
    int gtid = blockIdx.x * blockDim.x + threadIdx.x;
    int warp = gtid >> 5, lane = gtid & 31;
    if (warp >= NPART) return;
    const float* p = g_part + (size_t)warp * MAXB;
    float s = 0.f;
    for (int bq = lane; bq < nb; bq += 32) s += p[bq];
#pragma unroll
    for (int off = 16; off; off >>= 1)
        s += __shfl_down_sync(0xffffffffu, s, off);
    if (lane == 0) g_red[warp] = s;
}

// ---------------------------------------------------------------------------
// Pass 3 (tensor): out[:,0:32] = U @ (VtZ * D).
// U read as fp16 from g_Uh; M^T fp16 B-frags in registers.
// ---------------------------------------------------------------------------
__global__ __launch_bounds__(THREADS)
void pass3_kernel(float* __restrict__ out, int N)
{
    __shared__ __align__(16) __half Mt[32 * 40];   // [j][k], row stride 80 B
    __shared__ float sD;
    const int tid = threadIdx.x, lane = tid & 31, wid = tid >> 5;

    if (tid < 32) {
        float p = g_red[1024 + tid] * g_red[1056 + tid];
#pragma unroll
        for (int off = 16; off; off >>= 1)
            p += __shfl_down_sync(0xffffffffu, p, off);
        if (tid == 0) sD = 1.0f / (p / (float)N + EPSV);
    }
    __syncthreads();
    const float D = sD;
#pragma unroll
    for (int q = tid; q < 512; q += THREADS) {
        int j = q >> 4, kk = (q & 15) * 2;
        u32 val = h2(g_red[kk * 32 + j] * D, g_red[(kk + 1) * 32 + j] * D);
        *(u32*)((char*)Mt + j * 80 + kk * 2) = val;
    }
    __syncthreads();

    const u32 mtb = smem_u32(Mt);
    const u32 boffb = (u32)(((lane & 7) + ((lane >> 4) & 1) * 8) * 80
                            + ((lane >> 3) & 1) * 16);
    u32 Bf[4][2][2];
#pragma unroll
    for (int np = 0; np < 2; np++)
#pragma unroll
        for (int ks = 0; ks < 2; ks++) {
            u32 b0, b1, b2, b3;
            ldm_x4(mtb + boffb + np * 16 * 80 + ks * 32, b0, b1, b2, b3);
            Bf[2 * np][ks][0] = b0; Bf[2 * np][ks][1] = b1;
            Bf[2 * np + 1][ks][0] = b2; Bf[2 * np + 1][ks][1] = b3;
        }

    const int trow = blockIdx.x * 128 + wid * 16 + (lane >> 2);
    const bool ok1 = trow < N, ok2 = (trow + 8) < N;
    const __half* ur = g_Uh + (size_t)trow * 32 + (lane & 3) * 2;

    u32 af[2][4];
#pragma unroll
    for (int ks = 0; ks < 2; ks++) {
        af[ks][0] = ok1 ? *(const u32*)(ur + ks * 16)          : 0u;
        af[ks][1] = ok2 ? *(const u32*)(ur + ks * 16 + 8 * 32) : 0u;
        af[ks][2] = ok1 ? *(const u32*)(ur + ks * 16 + 8)      : 0u;
        af[ks][3] = ok2 ? *(const u32*)(ur + ks * 16 + 8 * 32 + 8) : 0u;
    }

    float acc[4][4];
#pragma unroll
    for (int nf = 0; nf < 4; nf++)
#pragma unroll
        for (int q = 0; q < 4; q++) acc[nf][q] = 0.f;

#pragma unroll
    for (int ks = 0; ks < 2; ks++)
#pragma unroll
        for (int nf = 0; nf < 4; nf++)
            mma16816(acc[nf][0], acc[nf][1], acc[nf][2], acc[nf][3],
                     af[ks][0], af[ks][1], af[ks][2], af[ks][3],
                     Bf[nf][ks][0], Bf[nf][ks][1]);

#pragma unroll
    for (int nf = 0; nf < 4; nf++) {
        const int col = nf * 8 + (lane & 3) * 2;
        if (ok1) *(float2*)(out + (size_t)trow * 64 + col) =
            make_float2(acc[nf][0], acc[nf][1]);
        if (ok2) *(float2*)(out + (size_t)(trow + 8) * 64 + col) =
            make_float2(acc[nf][2], acc[nf][3]);
    }
}

// ---------------------------------------------------------------------------
extern "C" void kernel_launch(void* const* d_in, const int* in_sizes, int n_in,
                              void* d_out, int out_size)
{
    const float* x = (const float*)d_in[0];
    const float* W = (const float*)d_in[1];
    const float* b = (const float*)d_in[2];
    float* out = (float*)d_out;

    const int N  = in_sizes[0] / D_IN;
    const int nb = (N + TM - 1) / TM;
    const int np = nb < GRIDP ? nb : GRIDP;

    cudaFuncSetAttribute(pass1_kernel,
                         cudaFuncAttributeMaxDynamicSharedMemorySize, DSM_B);

    dummy1_kernel<<<1, 32>>>();
    dummy2_kernel<<<1, 32>>>();
    wconv_kernel<<<(D_IN * C_OUT + 255) / 256, 256>>>(W);
    pass1_kernel<<<np, THREADS, DSM_B>>>(x, b, out, N, nb);
    reduce_kernel<<<(NPART * 32 + THREADS - 1) / THREADS, THREADS>>>(nb);
    pass3_kernel<<<(N + 127) / 128, THREADS>>>(out, N);
}